// round 3
// baseline (speedup 1.0000x reference)
#include <cuda_runtime.h>
#include <cstdint>

// Problem constants (fixed by setup_inputs)
#define BB   2
#define HHD  8
#define SEQ  8192
#define DKD  128
#define DVD  128
#define BT   64
#define NCH  128          // SEQ/BT
#define BHT  16           // BB*HHD
#define NCHUNKS 2048      // BHT*NCH
#define OSZ  16777216     // BHT*SEQ*DVD  (size of o)

typedef unsigned long long u64;

// ---- packed f32x2 helpers ----
__device__ __forceinline__ u64 pk2(float v) {
    u64 r; asm("mov.b64 %0,{%1,%1};" : "=l"(r) : "f"(v)); return r;
}
__device__ __forceinline__ u64 fma2(u64 a, u64 b, u64 c) {
    u64 d; asm("fma.rn.f32x2 %0,%1,%2,%3;" : "=l"(d) : "l"(a), "l"(b), "l"(c)); return d;
}
__device__ __forceinline__ u64 mul2(u64 a, u64 b) {
    u64 d; asm("mul.rn.f32x2 %0,%1,%2;" : "=l"(d) : "l"(a), "l"(b)); return d;
}
__device__ __forceinline__ float2 up2(u64 a) {
    float2 f; asm("mov.b64 {%0,%1},%2;" : "=f"(f.x), "=f"(f.y) : "l"(a)); return f;
}

// ---- cp.async helpers ----
__device__ __forceinline__ void cp16(uint32_t dst, const void* src) {
    asm volatile("cp.async.cg.shared.global [%0],[%1],16;" :: "r"(dst), "l"(src));
}
#define CP_COMMIT asm volatile("cp.async.commit_group;")
#define CP_WAIT0  asm volatile("cp.async.wait_group 0;")

// Scratch (device globals: allocation-free)
__device__ float g_qe [BHT*SEQ*DKD];     // q_norm*scale*eg          [row][K]
__device__ float g_krT[NCHUNKS*DKD*BT];  // k_norm*egl/eg transposed [chunk][K][row]
__device__ float g_w  [BHT*SEQ*DKD];     // -solved w                [row][K]
__device__ float g_u  [BHT*SEQ*DVD];     // solved u                 [row][V]
__device__ float g_A  [NCHUNKS*BT*BT];   // Aqk (zeros above diag)
__device__ float g_egl[NCHUNKS];         // eg at last row of chunk

#define P1_SMEM ((128*68*2 + 64*68 + 3*64)*4)
#define P2_SMEM ((64*132*2 + 2*128*68 + 2*64*68 + 2*64*16 + 128*20 + 64*20 + 128)*4)

// ---------------------------------------------------------------------------
// Phase 1: per-chunk (2048 CTAs).
// ---------------------------------------------------------------------------
__global__ void __launch_bounds__(256, 2) p1_kernel(
    const float* __restrict__ q, const float* __restrict__ k,
    const float* __restrict__ v, const float* __restrict__ g,
    const float* __restrict__ beta)
{
    extern __shared__ float sm[];
    float* skT = sm;                 // [128][68] k transposed (normalized)
    float* sqT = skT + 128*68;       // [128][68] q transposed (normalized*scale)
    float* sA0 = sqT + 128*68;       // [64][68]  strictly-lower A0
    float* seg = sA0 + 64*68;        // [64] exp(cumsum g)
    float* sie = seg + 64;           // [64] 1/seg
    float* sb  = sie + 64;           // [64] beta
    __shared__ float sgr[BT];

    const int cid = blockIdx.x;
    const int bh  = cid / NCH, n = cid % NCH;
    const int rowbase = bh*SEQ + n*BT;
    const int t = threadIdx.x;
    const int lane = t & 31, wid = t >> 5;

    if (t < BT) { sb[t] = beta[rowbase + t]; sgr[t] = g[rowbase + t]; }
    __syncthreads();
    if (t == 0) {
        float run = 0.f;
        for (int i = 0; i < BT; i++) {
            run += sgr[i];
            float e = expf(run);
            seg[i] = e; sie[i] = 1.f / e;
        }
        g_egl[cid] = seg[BT-1];
    }
    // normalize rows of q,k; store transposed
    for (int r = wid; r < BT; r += 8) {
        const float* kp = k + (size_t)(rowbase + r)*DKD;
        const float* qp = q + (size_t)(rowbase + r)*DKD;
        float k0=kp[lane],k1=kp[lane+32],k2=kp[lane+64],k3=kp[lane+96];
        float q0=qp[lane],q1=qp[lane+32],q2=qp[lane+64],q3=qp[lane+96];
        float ssk = k0*k0+k1*k1+k2*k2+k3*k3;
        float ssq = q0*q0+q1*q1+q2*q2+q3*q3;
        #pragma unroll
        for (int o = 16; o; o >>= 1) {
            ssk += __shfl_xor_sync(0xffffffffu, ssk, o);
            ssq += __shfl_xor_sync(0xffffffffu, ssq, o);
        }
        float ik = 1.f/(sqrtf(ssk)+1e-6f);
        float iq = 0.08838834764831845f/(sqrtf(ssq)+1e-6f);  // scale=K^-0.5 folded in
        skT[(lane    )*68+r]=k0*ik; skT[(lane+32)*68+r]=k1*ik;
        skT[(lane+64)*68+r]=k2*ik; skT[(lane+96)*68+r]=k3*ik;
        sqT[(lane    )*68+r]=q0*iq; sqT[(lane+32)*68+r]=q1*iq;
        sqT[(lane+64)*68+r]=q2*iq; sqT[(lane+96)*68+r]=q3*iq;
    }
    __syncthreads();

    // Fused A0 (k·k^T) + Aqk (q·k^T): 4x4 register tiles, packed f32x2
    const int ty4 = (t >> 4)*4, tx4 = (t & 15)*4;
    u64 aK01[4], aK23[4], aQ01[4], aQ23[4];
    #pragma unroll
    for (int z = 0; z < 4; z++) { aK01[z]=0ull; aK23[z]=0ull; aQ01[z]=0ull; aQ23[z]=0ull; }
    #pragma unroll 4
    for (int kk = 0; kk < DKD; kk++) {
        const float* rk = skT + kk*68;
        ulonglong2 b   = *(const ulonglong2*)(rk + tx4);
        float4 kv4 = *(const float4*)(rk + ty4);
        float4 qv4 = *(const float4*)(sqT + kk*68 + ty4);
        float kvs[4] = {kv4.x,kv4.y,kv4.z,kv4.w};
        float qvs[4] = {qv4.x,qv4.y,qv4.z,qv4.w};
        #pragma unroll
        for (int ii = 0; ii < 4; ii++) {
            u64 kp2 = pk2(kvs[ii]), qp2 = pk2(qvs[ii]);
            aK01[ii] = fma2(kp2, b.x, aK01[ii]);
            aK23[ii] = fma2(kp2, b.y, aK23[ii]);
            aQ01[ii] = fma2(qp2, b.x, aQ01[ii]);
            aQ23[ii] = fma2(qp2, b.y, aQ23[ii]);
        }
    }
    #pragma unroll
    for (int ii = 0; ii < 4; ii++) {
        int i = ty4 + ii;
        float segi = seg[i], bi = sb[i];
        float2 ka = up2(aK01[ii]), kb = up2(aK23[ii]);
        float2 qa = up2(aQ01[ii]), qb = up2(aQ23[ii]);
        float aKv[4] = {ka.x,ka.y,kb.x,kb.y};
        float aQv[4] = {qa.x,qa.y,qb.x,qb.y};
        #pragma unroll
        for (int jj = 0; jj < 4; jj++) {
            int j = tx4 + jj;
            float rat = segi * sie[j];        // exp(gc_i - gc_j)
            if (j < i) sA0[i*68+j] = aKv[jj]*rat*bi;
            float f = (j < i) ? rat : ((j == i) ? 1.f : 0.f);
            g_A[(size_t)cid*4096 + i*64 + j] = aQv[jj]*f;
        }
    }
    __syncthreads();

    // Emit qe = q*scale*eg (row-major)
    {
        int c = t & 127, hb = t >> 7;
        for (int i = hb*32; i < hb*32 + 32; i++)
            g_qe[(size_t)(rowbase+i)*DKD + c] = sqT[c*68+i]*seg[i];
    }
    // Emit krT = k_norm*egl/eg, transposed layout [chunk][K][row]
    {
        int c = t >> 1, half = (t & 1)*32;
        float egl2 = seg[BT-1];
        size_t kb = (size_t)cid*8192 + (size_t)c*64 + half;
        #pragma unroll
        for (int i4 = 0; i4 < 32; i4 += 4) {
            float4 kv = *(const float4*)&skT[c*68 + half + i4];
            float4 iv = *(const float4*)&sie[half + i4];
            float4 o;
            o.x = kv.x*egl2*iv.x; o.y = kv.y*egl2*iv.y;
            o.z = kv.z*egl2*iv.z; o.w = kv.w*egl2*iv.w;
            *(float4*)&g_krT[kb + i4] = o;
        }
    }

    // Unit-lower triangular solve: ALL 256 threads, one column each.
    // cols 0..127: k-rhs (beta*k_norm*eg) -> -w ; cols 128..255: v-rhs -> u
    {
        float x[64];
        if (t < 128) {
            #pragma unroll
            for (int i = 0; i < 64; i++) x[i] = sb[i]*skT[t*68+i]*seg[i];
        } else {
            const float* vp = v + (size_t)rowbase*DVD + (t - 128);
            #pragma unroll
            for (int i = 0; i < 64; i++) x[i] = sb[i]*vp[i*DVD];
        }
        #pragma unroll
        for (int i = 1; i < 64; i++) {
            float s0 = 0.f, s1 = 0.f, s2 = 0.f, s3 = 0.f;
            int j = 0;
            #pragma unroll
            for (; j + 4 <= i; j += 4) {
                float4 a4 = *(const float4*)&sA0[i*68+j];
                s0 += a4.x*x[j]; s1 += a4.y*x[j+1];
                s2 += a4.z*x[j+2]; s3 += a4.w*x[j+3];
            }
            #pragma unroll
            for (; j < i; j++) s0 += sA0[i*68+j]*x[j];
            x[i] -= (s0 + s1) + (s2 + s3);
        }
        if (t < 128) {
            #pragma unroll
            for (int i = 0; i < 64; i++)
                g_w[(size_t)(rowbase+i)*DKD + t] = -x[i];   // store NEGATED w
        } else {
            #pragma unroll
            for (int i = 0; i < 64; i++)
                g_u[(size_t)(rowbase+i)*DVD + (t-128)] = x[i];
        }
    }
}

// ---------------------------------------------------------------------------
// Phase 2: state recurrence. 128 CTAs = 16 (b,h) x 8 V-slices of width 16.
// 512 threads. S kept in registers (loop3 owner mapping), mirrored to smem
// for loop1 reads. Split accumulator chains. cp.async two-stage prefetch.
// ---------------------------------------------------------------------------
__device__ __forceinline__ void p2_pref_a(
    int bh, int n, int buf, int vb, int t,
    uint32_t a_skrT, uint32_t a_sA, uint32_t a_su)
{
    const size_t rb = (size_t)bh*SEQ + (size_t)n*BT;
    const float* kg = g_krT + (size_t)(bh*NCH + n)*8192;
    const float* Ag = g_A   + (size_t)(bh*NCH + n)*4096;
    #pragma unroll
    for (int it = 0; it < 4; it++) {
        int idx = t + 512*it;                       // 0..2047
        int row = idx >> 4, col = (idx & 15)*4;
        cp16(a_skrT + (uint32_t)buf*34816 + (uint32_t)(row*68+col)*4, kg + idx*4);
    }
    #pragma unroll
    for (int it = 0; it < 2; it++) {
        int idx = t + 512*it;                       // 0..1023
        int row = idx >> 4, col = (idx & 15)*4;
        cp16(a_sA + (uint32_t)buf*17408 + (uint32_t)(row*68+col)*4, Ag + idx*4);
    }
    if (t < 256) {
        int row = t >> 2, col = (t & 3)*4;
        cp16(a_su + (uint32_t)buf*4096 + (uint32_t)t*16,
             g_u + (rb + row)*DVD + vb + col);
    }
}

__device__ __forceinline__ void p2_pref_b(
    int bh, int n, int t, uint32_t a_sw, uint32_t a_sqe)
{
    const size_t rb = (size_t)bh*SEQ + (size_t)n*BT;
    const float* wg = g_w  + rb*DKD;
    const float* qg = g_qe + rb*DKD;
    #pragma unroll
    for (int it = 0; it < 4; it++) {
        int idx = t + 512*it;                       // 0..2047
        int row = idx >> 5, col = (idx & 31)*4;
        cp16(a_sw  + (uint32_t)(row*132+col)*4, wg + idx*4);
        cp16(a_sqe + (uint32_t)(row*132+col)*4, qg + idx*4);
    }
}

__global__ void __launch_bounds__(512, 1) p2_kernel(float* __restrict__ out, int write_sf)
{
    extern __shared__ float sm[];
    float* sw   = sm;                   // [64][132]
    float* sqe  = sw   + 64*132;        // [64][132]
    float* skrT = sqe  + 64*132;        // [2][128][68]
    float* sA   = skrT + 2*128*68;      // [2][64][68]
    float* su   = sA   + 2*64*68;       // [2][64][16]
    float* sS   = su   + 2*64*16;       // [128][20] state mirror
    float* svn  = sS   + 128*20;        // [64][20]  v_new
    float* segl = svn  + 64*20;         // [128]

    const int t  = threadIdx.x;
    const int bh = blockIdx.x >> 3;
    const int vb = (blockIdx.x & 7) * 16;

    const uint32_t a_sw   = (uint32_t)__cvta_generic_to_shared(sw);
    const uint32_t a_sqe  = (uint32_t)__cvta_generic_to_shared(sqe);
    const uint32_t a_skrT = (uint32_t)__cvta_generic_to_shared(skrT);
    const uint32_t a_sA   = (uint32_t)__cvta_generic_to_shared(sA);
    const uint32_t a_su   = (uint32_t)__cvta_generic_to_shared(su);

    for (int i = t; i < 128*20; i += 512) sS[i] = 0.f;
    if (t < 128) segl[t] = g_egl[bh*NCH + t];

    // S in registers: thread owns S[kk2][c4..c4+3]
    const int r   = t >> 3, cq = t & 7;        // loop1/2: row r, cols cq*2..+1
    const int kk2 = t >> 2, c4 = (t & 3)*4;    // loop3: S float4
    u64 S0 = 0ull, S1 = 0ull;

    p2_pref_a(bh, 0, 0, vb, t, a_skrT, a_sA, a_su);
    p2_pref_b(bh, 0, t, a_sw, a_sqe);
    CP_COMMIT;

    const u64 one = pk2(1.0f);

    for (int n = 0; n < NCH; n++) {
        const int buf = n & 1;
        CP_WAIT0;
        __syncthreads();

        if (n + 1 < NCH) {
            p2_pref_a(bh, n+1, buf^1, vb, t, a_skrT, a_sA, a_su);
            CP_COMMIT;
        }

        const size_t rb = (size_t)bh*SEQ + (size_t)n*BT;

        // ---- loop1: v_new = u + (-w)@S ; o_inter = qe@S. Split-k chains.
        u64 v_a = *(const u64*)&su[buf*1024 + r*16 + cq*2];
        u64 v_b = 0ull, o_a = 0ull, o_b = 0ull;
        const float* swr = sw  + r*132;
        const float* sqr = sqe + r*132;
        #pragma unroll
        for (int kk = 0; kk < 64; kk += 4) {
            float4 w4 = *(const float4*)(swr + kk);
            float4 q4 = *(const float4*)(sqr + kk);
            float ws[4] = {w4.x,w4.y,w4.z,w4.w};
            float qs[4] = {q4.x,q4.y,q4.z,q4.w};
            #pragma unroll
            for (int e = 0; e < 4; e++) {
                u64 s = *(const u64*)&sS[(kk+e)*20 + cq*2];
                v_a = fma2(pk2(ws[e]), s, v_a);
                o_a = fma2(pk2(qs[e]), s, o_a);
            }
        }
        #pragma unroll
        for (int kk = 64; kk < 128; kk += 4) {
            float4 w4 = *(const float4*)(swr + kk);
            float4 q4 = *(const float4*)(sqr + kk);
            float ws[4] = {w4.x,w4.y,w4.z,w4.w};
            float qs[4] = {q4.x,q4.y,q4.z,q4.w};
            #pragma unroll
            for (int e = 0; e < 4; e++) {
                u64 s = *(const u64*)&sS[(kk+e)*20 + cq*2];
                v_b = fma2(pk2(ws[e]), s, v_b);
                o_b = fma2(pk2(qs[e]), s, o_b);
            }
        }
        u64 vfin = fma2(one, v_b, v_a);
        *(u64*)&svn[r*20 + cq*2] = vfin;
        __syncthreads();

        if (n + 1 < NCH) {
            p2_pref_b(bh, n+1, t, a_sw, a_sqe);
            CP_COMMIT;
        }

        // ---- loop2: o += Aqk @ v_new  (alternate chains by parity)
        const float* sAr = sA + buf*4352 + r*68;
        #pragma unroll
        for (int j = 0; j < BT; j += 4) {
            float4 a4 = *(const float4*)(sAr + j);
            float as[4] = {a4.x,a4.y,a4.z,a4.w};
            #pragma unroll
            for (int e = 0; e < 4; e++) {
                u64 vv = *(const u64*)&svn[(j+e)*20 + cq*2];
                if (e & 1) o_b = fma2(pk2(as[e]), vv, o_b);
                else       o_a = fma2(pk2(as[e]), vv, o_a);
            }
        }
        {
            float2 ov = up2(fma2(one, o_b, o_a));
            *(float2*)(out + (rb + r)*DVD + vb + cq*2) = ov;
        }

        // ---- loop3: S = egl*S + kr^T @ v_new  (register state, split chains)
        {
            const float* skp = skrT + buf*8704 + kk2*68;
            u64 eg2 = pk2(segl[n]);
            u64 a0 = mul2(eg2, S0), a1 = mul2(eg2, S1);
            u64 b0 = 0ull,          b1 = 0ull;
            #pragma unroll
            for (int r2 = 0; r2 < 32; r2 += 4) {
                float4 kr4 = *(const float4*)(skp + r2);
                float ks[4] = {kr4.x,kr4.y,kr4.z,kr4.w};
                #pragma unroll
                for (int e = 0; e < 4; e++) {
                    ulonglong2 vv = *(const ulonglong2*)&svn[(r2+e)*20 + c4];
                    u64 kp = pk2(ks[e]);
                    a0 = fma2(kp, vv.x, a0); a1 = fma2(kp, vv.y, a1);
                }
            }
            #pragma unroll
            for (int r2 = 32; r2 < 64; r2 += 4) {
                float4 kr4 = *(const float4*)(skp + r2);
                float ks[4] = {kr4.x,kr4.y,kr4.z,kr4.w};
                #pragma unroll
                for (int e = 0; e < 4; e++) {
                    ulonglong2 vv = *(const ulonglong2*)&svn[(r2+e)*20 + c4];
                    u64 kp = pk2(ks[e]);
                    b0 = fma2(kp, vv.x, b0); b1 = fma2(kp, vv.y, b1);
                }
            }
            S0 = fma2(one, b0, a0);
            S1 = fma2(one, b1, a1);
            *(ulonglong2*)&sS[kk2*20 + c4] = make_ulonglong2(S0, S1);
        }
        // next iteration's top barrier orders sS writes vs loop1 reads
    }

    if (write_sf) {
        float2 p0 = up2(S0), p1 = up2(S1);
        float* dst = out + OSZ + ((size_t)bh*DKD + kk2)*DVD + vb + c4;
        *(float4*)dst = make_float4(p0.x, p0.y, p1.x, p1.y);
    }
}

// ---------------------------------------------------------------------------
extern "C" void kernel_launch(void* const* d_in, const int* in_sizes, int n_in,
                              void* d_out, int out_size)
{
    const float* q    = (const float*)d_in[0];
    const float* k    = (const float*)d_in[1];
    const float* v    = (const float*)d_in[2];
    const float* g    = (const float*)d_in[3];
    const float* beta = (const float*)d_in[4];
    float* out = (float*)d_out;

    cudaFuncSetAttribute(p1_kernel, cudaFuncAttributeMaxDynamicSharedMemorySize, P1_SMEM);
    cudaFuncSetAttribute(p2_kernel, cudaFuncAttributeMaxDynamicSharedMemorySize, P2_SMEM);

    p1_kernel<<<NCHUNKS, 256, P1_SMEM>>>(q, k, v, g, beta);

    int wsf = (out_size > OSZ) ? 1 : 0;
    p2_kernel<<<BHT*8, 512, P2_SMEM>>>(out, wsf);
}

// round 4
// speedup vs baseline: 2.4209x; 2.4209x over previous
#include <cuda_runtime.h>
#include <cstdint>

// Problem constants (fixed by setup_inputs)
#define SEQ  8192
#define DKD  128
#define DVD  128
#define BT   64
#define NCH  128          // SEQ/BT
#define BHT  16           // BB*HHD
#define NCHUNKS 2048      // BHT*NCH
#define OSZ  16777216     // BHT*SEQ*DVD  (size of o)

typedef unsigned long long u64;

// ---- tf32 helpers ----
__device__ __forceinline__ uint32_t tf32r(float f) {
    uint32_t u; asm("cvt.rna.tf32.f32 %0,%1;" : "=r"(u) : "f"(f)); return u;
}
__device__ __forceinline__ void mma8(float& d0, float& d1, float& d2, float& d3,
    uint32_t a0, uint32_t a1, uint32_t a2, uint32_t a3, uint32_t b0, uint32_t b1) {
    asm("mma.sync.aligned.m16n8k8.row.col.f32.tf32.tf32.f32 "
        "{%0,%1,%2,%3},{%4,%5,%6,%7},{%8,%9},{%0,%1,%2,%3};"
        : "+f"(d0), "+f"(d1), "+f"(d2), "+f"(d3)
        : "r"(a0), "r"(a1), "r"(a2), "r"(a3), "r"(b0), "r"(b1));
}

// ---- packed f32x2 helpers (p1 matmul) ----
__device__ __forceinline__ u64 pk2(float v) {
    u64 r; asm("mov.b64 %0,{%1,%1};" : "=l"(r) : "f"(v)); return r;
}
__device__ __forceinline__ u64 fma2(u64 a, u64 b, u64 c) {
    u64 d; asm("fma.rn.f32x2 %0,%1,%2,%3;" : "=l"(d) : "l"(a), "l"(b), "l"(c)); return d;
}
__device__ __forceinline__ float2 up2(u64 a) {
    float2 f; asm("mov.b64 {%0,%1},%2;" : "=f"(f.x), "=f"(f.y) : "l"(a)); return f;
}

// ---- cp.async ----
__device__ __forceinline__ void cp16(uint32_t dst, const void* src) {
    asm volatile("cp.async.cg.shared.global [%0],[%1],16;" :: "r"(dst), "l"(src));
}
#define CP_COMMIT asm volatile("cp.async.commit_group;")
#define CP_WAIT0  asm volatile("cp.async.wait_group 0;")

// Scratch (device globals; tf32 bit patterns in uint32)
// Fragment-major layouts: element (block b, lane l, reg j) at [b*128 + l*4 + j].
__device__ uint32_t g_wf [NCHUNKS*8192];   // -w    : blocks b=(i>>4)*16+(c>>3)
__device__ uint32_t g_qef[NCHUNKS*8192];   // qe    : same block layout
__device__ uint32_t g_krf[NCHUNKS*8192];   // krT   : blocks b=(c>>4)*8+(i>>3)
__device__ uint32_t g_Af [NCHUNKS*4096];   // Aqk   : blocks b=(i>>4)*8+(j>>3)
__device__ float    g_u  [BHT*SEQ*DVD];    // u fp32 [row][V]
__device__ float    g_egl[NCHUNKS];

#define P1_SMEM ((8704*2 + 4352*2 + 3*64)*4)

// p2 smem word offsets
#define OFF_WF   0                 // 8192  (single buf)
#define OFF_QEF  8192              // 8192  (single buf)
#define OFF_KRF  16384             // 2*8192
#define OFF_AF   32768             // 2*4096
#define OFF_SU   40960             // 2*1024 (float)
#define OFF_SS   43008             // 128*24 tf32
#define OFF_SVN  46080             // 64*24 tf32
#define OFF_EGL  47616             // 128 float
#define P2_WORDS 47744
#define P2_SMEM  (P2_WORDS*4)

// ---------------------------------------------------------------------------
// Phase 1: per-chunk (2048 CTAs). fp32 throughout; emits tf32 fragment tiles.
// ---------------------------------------------------------------------------
__global__ void __launch_bounds__(256, 2) p1_kernel(
    const float* __restrict__ q, const float* __restrict__ k,
    const float* __restrict__ v, const float* __restrict__ g,
    const float* __restrict__ beta)
{
    extern __shared__ float sm[];
    float* skT = sm;                 // [128][68] k transposed (normalized)
    float* sqT = skT + 8704;         // [128][68] q transposed (normalized*scale); later: -w staged
    float* sA0 = sqT + 8704;         // [64][68]  strictly-lower A0
    float* sAq = sA0 + 4352;         // [64][68]  full Aqk
    float* seg = sAq + 4352;         // [64] exp(cumsum g)
    float* sie = seg + 64;           // [64] 1/seg
    float* sb  = sie + 64;           // [64] beta
    __shared__ float sgr[BT];

    const int cid = blockIdx.x;
    const int bh  = cid / NCH, n = cid % NCH;
    const int rowbase = bh*SEQ + n*BT;
    const int t = threadIdx.x;
    const int lane = t & 31, wid = t >> 5;

    if (t < BT) { sb[t] = beta[rowbase + t]; sgr[t] = g[rowbase + t]; }
    __syncthreads();
    if (t == 0) {
        float run = 0.f;
        for (int i = 0; i < BT; i++) {
            run += sgr[i];
            float e = expf(run);
            seg[i] = e; sie[i] = 1.f / e;
        }
        g_egl[cid] = seg[BT-1];
    }
    // normalize rows of q,k; store transposed
    for (int r = wid; r < BT; r += 8) {
        const float* kp = k + (size_t)(rowbase + r)*DKD;
        const float* qp = q + (size_t)(rowbase + r)*DKD;
        float k0=kp[lane],k1=kp[lane+32],k2=kp[lane+64],k3=kp[lane+96];
        float q0=qp[lane],q1=qp[lane+32],q2=qp[lane+64],q3=qp[lane+96];
        float ssk = k0*k0+k1*k1+k2*k2+k3*k3;
        float ssq = q0*q0+q1*q1+q2*q2+q3*q3;
        #pragma unroll
        for (int o = 16; o; o >>= 1) {
            ssk += __shfl_xor_sync(0xffffffffu, ssk, o);
            ssq += __shfl_xor_sync(0xffffffffu, ssq, o);
        }
        float ik = 1.f/(sqrtf(ssk)+1e-6f);
        float iq = 0.08838834764831845f/(sqrtf(ssq)+1e-6f);  // K^-0.5 folded in
        skT[(lane    )*68+r]=k0*ik; skT[(lane+32)*68+r]=k1*ik;
        skT[(lane+64)*68+r]=k2*ik; skT[(lane+96)*68+r]=k3*ik;
        sqT[(lane    )*68+r]=q0*iq; sqT[(lane+32)*68+r]=q1*iq;
        sqT[(lane+64)*68+r]=q2*iq; sqT[(lane+96)*68+r]=q3*iq;
    }
    __syncthreads();

    // Fused A0 (k·k^T) + Aqk (q·k^T): 4x4 register tiles, packed f32x2
    const int ty4 = (t >> 4)*4, tx4 = (t & 15)*4;
    u64 aK01[4], aK23[4], aQ01[4], aQ23[4];
    #pragma unroll
    for (int z = 0; z < 4; z++) { aK01[z]=0ull; aK23[z]=0ull; aQ01[z]=0ull; aQ23[z]=0ull; }
    #pragma unroll 4
    for (int kk = 0; kk < DKD; kk++) {
        const float* rk = skT + kk*68;
        ulonglong2 b   = *(const ulonglong2*)(rk + tx4);
        float4 kv4 = *(const float4*)(rk + ty4);
        float4 qv4 = *(const float4*)(sqT + kk*68 + ty4);
        float kvs[4] = {kv4.x,kv4.y,kv4.z,kv4.w};
        float qvs[4] = {qv4.x,qv4.y,qv4.z,qv4.w};
        #pragma unroll
        for (int ii = 0; ii < 4; ii++) {
            u64 kp2 = pk2(kvs[ii]), qp2 = pk2(qvs[ii]);
            aK01[ii] = fma2(kp2, b.x, aK01[ii]);
            aK23[ii] = fma2(kp2, b.y, aK23[ii]);
            aQ01[ii] = fma2(qp2, b.x, aQ01[ii]);
            aQ23[ii] = fma2(qp2, b.y, aQ23[ii]);
        }
    }
    #pragma unroll
    for (int ii = 0; ii < 4; ii++) {
        int i = ty4 + ii;
        float segi = seg[i], bi = sb[i];
        float2 ka = up2(aK01[ii]), kb = up2(aK23[ii]);
        float2 qa = up2(aQ01[ii]), qb = up2(aQ23[ii]);
        float aKv[4] = {ka.x,ka.y,kb.x,kb.y};
        float aQv[4] = {qa.x,qa.y,qb.x,qb.y};
        #pragma unroll
        for (int jj = 0; jj < 4; jj++) {
            int j = tx4 + jj;
            float rat = segi * sie[j];        // exp(gc_i - gc_j)
            if (j < i) sA0[i*68+j] = aKv[jj]*rat*bi;
            float f = (j < i) ? rat : ((j == i) ? 1.f : 0.f);
            sAq[i*68+j] = aQv[jj]*f;
        }
    }
    __syncthreads();

    // ---- Fragment emits (coalesced STG.128). blocks: lane l, regs j=0..3 ----
    // qe: A-layout blocks b = br*16+kc; row i=16br+(l>>2)+8*(j&1); col c=8kc+(l&3)+4*(j>>1)
    for (int task = t; task < 2048; task += 256) {
        int b = task >> 5, l = task & 31;
        int br = b >> 4, kc = b & 15;
        int i0 = 16*br + (l>>2), c0 = 8*kc + (l&3);
        uint4 o;
        o.x = tf32r(sqT[(c0  )*68 + i0  ] * seg[i0  ]);
        o.y = tf32r(sqT[(c0  )*68 + i0+8] * seg[i0+8]);
        o.z = tf32r(sqT[(c0+4)*68 + i0  ] * seg[i0  ]);
        o.w = tf32r(sqT[(c0+4)*68 + i0+8] * seg[i0+8]);
        *(uint4*)&g_qef[(size_t)cid*8192 + b*128 + l*4] = o;
    }
    // krT: blocks b = cr*8+kc; Mrow c=16cr+(l>>2)+8*(j&1) (state dim); Kcol i=8kc+(l&3)+4*(j>>1)
    {
        float egl2 = seg[BT-1];
        for (int task = t; task < 2048; task += 256) {
            int b = task >> 5, l = task & 31;
            int cr = b >> 3, kc = b & 7;
            int c0 = 16*cr + (l>>2), i0 = 8*kc + (l&3);
            uint4 o;
            o.x = tf32r(skT[(c0  )*68 + i0  ] * egl2 * sie[i0  ]);
            o.y = tf32r(skT[(c0+8)*68 + i0  ] * egl2 * sie[i0  ]);
            o.z = tf32r(skT[(c0  )*68 + i0+4] * egl2 * sie[i0+4]);
            o.w = tf32r(skT[(c0+8)*68 + i0+4] * egl2 * sie[i0+4]);
            *(uint4*)&g_krf[(size_t)cid*8192 + b*128 + l*4] = o;
        }
    }
    // Aqk: blocks b = br*8+kc; row i=16br+(l>>2)+8*(j&1); col jc=8kc+(l&3)+4*(j>>1)
    for (int task = t; task < 1024; task += 256) {
        int b = task >> 5, l = task & 31;
        int br = b >> 3, kc = b & 7;
        int i0 = 16*br + (l>>2), j0 = 8*kc + (l&3);
        uint4 o;
        o.x = tf32r(sAq[(i0  )*68 + j0  ]);
        o.y = tf32r(sAq[(i0+8)*68 + j0  ]);
        o.z = tf32r(sAq[(i0  )*68 + j0+4]);
        o.w = tf32r(sAq[(i0+8)*68 + j0+4]);
        *(uint4*)&g_Af[(size_t)cid*4096 + b*128 + l*4] = o;
    }
    __syncthreads();   // emits done before solve overwrites sqT

    // Unit-lower triangular solve: t<128 k-cols -> stage -w into sqT; t>=128 v-cols -> u
    {
        float x[64];
        if (t < 128) {
            #pragma unroll
            for (int i = 0; i < 64; i++) x[i] = sb[i]*skT[t*68+i]*seg[i];
        } else {
            const float* vp = v + (size_t)rowbase*DVD + (t - 128);
            #pragma unroll
            for (int i = 0; i < 64; i++) x[i] = sb[i]*vp[i*DVD];
        }
        #pragma unroll
        for (int i = 1; i < 64; i++) {
            float s0 = 0.f, s1 = 0.f, s2 = 0.f, s3 = 0.f;
            int j = 0;
            #pragma unroll
            for (; j + 4 <= i; j += 4) {
                float4 a4 = *(const float4*)&sA0[i*68+j];
                s0 += a4.x*x[j]; s1 += a4.y*x[j+1];
                s2 += a4.z*x[j+2]; s3 += a4.w*x[j+3];
            }
            #pragma unroll
            for (; j < i; j++) s0 += sA0[i*68+j]*x[j];
            x[i] -= (s0 + s1) + (s2 + s3);
        }
        if (t < 128) {
            #pragma unroll
            for (int i = 0; i < 64; i++) sqT[t*68+i] = -x[i];   // stage NEGATED w
        } else {
            #pragma unroll
            for (int i = 0; i < 64; i++)
                g_u[(size_t)(rowbase+i)*DVD + (t-128)] = x[i];
        }
    }
    __syncthreads();

    // -w fragment emit (same block layout as qe)
    for (int task = t; task < 2048; task += 256) {
        int b = task >> 5, l = task & 31;
        int br = b >> 4, kc = b & 15;
        int i0 = 16*br + (l>>2), c0 = 8*kc + (l&3);
        uint4 o;
        o.x = tf32r(sqT[(c0  )*68 + i0  ]);
        o.y = tf32r(sqT[(c0  )*68 + i0+8]);
        o.z = tf32r(sqT[(c0+4)*68 + i0  ]);
        o.w = tf32r(sqT[(c0+4)*68 + i0+8]);
        *(uint4*)&g_wf[(size_t)cid*8192 + b*128 + l*4] = o;
    }
}

// ---------------------------------------------------------------------------
// Phase 2: state recurrence on tf32 mma.sync. 128 CTAs (16 bh x 8 V-slices),
// 256 threads = 8 warps. S persists in fp32 accumulator registers.
// ---------------------------------------------------------------------------
__device__ __forceinline__ void p2_pref_a(int cid, size_t rb, int buf, int vb, int t,
                                          uint32_t sbase)
{
    const uint32_t* kg = g_krf + (size_t)cid*8192;
    const uint32_t* Ag = g_Af  + (size_t)cid*4096;
    #pragma unroll
    for (int it = 0; it < 8; it++) {
        int idx = t + 256*it;                 // uint4 idx 0..2047
        cp16(sbase + (OFF_KRF + buf*8192 + idx*4)*4, kg + idx*4);
    }
    #pragma unroll
    for (int it = 0; it < 4; it++) {
        int idx = t + 256*it;                 // 0..1023
        cp16(sbase + (OFF_AF + buf*4096 + idx*4)*4, Ag + idx*4);
    }
    {
        int row = t >> 2, col = (t & 3)*4;
        cp16(sbase + (OFF_SU + buf*1024 + t*4)*4, g_u + (rb + row)*DVD + vb + col);
    }
}
__device__ __forceinline__ void p2_pref_b(int cid, int t, uint32_t sbase)
{
    const uint32_t* wg = g_wf  + (size_t)cid*8192;
    const uint32_t* qg = g_qef + (size_t)cid*8192;
    #pragma unroll
    for (int it = 0; it < 8; it++) {
        int idx = t + 256*it;
        cp16(sbase + (OFF_WF  + idx*4)*4, wg + idx*4);
        cp16(sbase + (OFF_QEF + idx*4)*4, qg + idx*4);
    }
}

__global__ void __launch_bounds__(256, 1) p2_kernel(float* __restrict__ out, int write_sf)
{
    extern __shared__ uint32_t smu[];
    float* sf = (float*)smu;

    const int t  = threadIdx.x;
    const int w  = t >> 5, l = t & 31;
    const int g  = l >> 2, tig = l & 3;
    const int mr = w >> 1, nt = w & 1;      // L1/L2 tile: rows 16mr.., cols 8nt..
    const int bh = blockIdx.x >> 3;
    const int vb = (blockIdx.x & 7) * 16;

    const uint32_t sbase = (uint32_t)__cvta_generic_to_shared(smu);

    for (int i = t; i < 3072; i += 256) smu[OFF_SS + i] = 0u;
    if (t < 128) sf[OFF_EGL + t] = g_egl[bh*NCH + t];

    // persistent S (fp32): warp owns rows 16w+g, 16w+g+8; cols 2tig,2tig+1 and +8
    float S0=0.f,S1=0.f,S2=0.f,S3=0.f,S4=0.f,S5=0.f,S6=0.f,S7=0.f;

    {
        size_t rb0 = (size_t)bh*SEQ;
        p2_pref_a(bh*NCH, rb0, 0, vb, t, sbase);
        p2_pref_b(bh*NCH, t, sbase);
        CP_COMMIT;
    }

    const uint4* wfB = (const uint4*)(smu + OFF_WF);
    const uint4* qfB = (const uint4*)(smu + OFF_QEF);
    const uint4* kfB = (const uint4*)(smu + OFF_KRF);
    const uint4* afB = (const uint4*)(smu + OFF_AF);

    for (int n = 0; n < NCH; n++) {
        const int buf = n & 1;
        const size_t rb = (size_t)bh*SEQ + (size_t)n*BT;
        CP_WAIT0;
        __syncthreads();

        if (n + 1 < NCH)
            p2_pref_a(bh*NCH + n + 1, rb + BT, buf^1, vb, t, sbase);
        CP_COMMIT;

        // ---- L1: v = u + (-w)@S ; o = qe@S   (K=128, 16 chunks)
        float v0,v1,v2,v3, o0=0.f,o1=0.f,o2=0.f,o3=0.f;
        {
            const float* suB = sf + OFF_SU + buf*1024;
            float2 ua = *(const float2*)&suB[(16*mr + g    )*16 + nt*8 + 2*tig];
            float2 ub = *(const float2*)&suB[(16*mr + g + 8)*16 + nt*8 + 2*tig];
            v0 = ua.x; v1 = ua.y; v2 = ub.x; v3 = ub.y;
        }
        #pragma unroll
        for (int kc = 0; kc < 16; kc++) {
            uint4 aw = wfB[(mr*16 + kc)*32 + l];
            uint4 aq = qfB[(mr*16 + kc)*32 + l];
            uint32_t b0 = smu[OFF_SS + (8*kc     + tig)*24 + nt*8 + g];
            uint32_t b1 = smu[OFF_SS + (8*kc + 4 + tig)*24 + nt*8 + g];
            mma8(v0,v1,v2,v3, aw.x,aw.y,aw.z,aw.w, b0,b1);
            mma8(o0,o1,o2,o3, aq.x,aq.y,aq.z,aq.w, b0,b1);
        }
        // store v_new (tf32) to svn
        {
            uint2 pa, pb;
            pa.x = tf32r(v0); pa.y = tf32r(v1);
            pb.x = tf32r(v2); pb.y = tf32r(v3);
            *(uint2*)&smu[OFF_SVN + (16*mr + g    )*24 + nt*8 + 2*tig] = pa;
            *(uint2*)&smu[OFF_SVN + (16*mr + g + 8)*24 + nt*8 + 2*tig] = pb;
        }
        __syncthreads();

        if (n + 1 < NCH) {
            p2_pref_b(bh*NCH + n + 1, t, sbase);
            CP_COMMIT;
        }

        // ---- L2: o += Aqk @ v_new   (K=64, 8 chunks)
        #pragma unroll
        for (int kc = 0; kc < 8; kc++) {
            uint4 aa = afB[buf*1024 + (mr*8 + kc)*32 + l];
            uint32_t b0 = smu[OFF_SVN + (8*kc     + tig)*24 + nt*8 + g];
            uint32_t b1 = smu[OFF_SVN + (8*kc + 4 + tig)*24 + nt*8 + g];
            mma8(o0,o1,o2,o3, aa.x,aa.y,aa.z,aa.w, b0,b1);
        }
        {
            float* dst0 = out + (rb + 16*mr + g    )*DVD + vb + nt*8 + 2*tig;
            float* dst1 = out + (rb + 16*mr + g + 8)*DVD + vb + nt*8 + 2*tig;
            *(float2*)dst0 = make_float2(o0, o1);
            *(float2*)dst1 = make_float2(o2, o3);
        }

        // ---- L3: S = egl*S + krT @ v_new  (M=128 strip per warp, K=64)
        {
            float egl = sf[OFF_EGL + n];
            S0*=egl; S1*=egl; S2*=egl; S3*=egl; S4*=egl; S5*=egl; S6*=egl; S7*=egl;
            #pragma unroll
            for (int kc = 0; kc < 8; kc++) {
                uint4 ak = kfB[buf*2048 + (w*8 + kc)*32 + l];
                uint32_t b0 = smu[OFF_SVN + (8*kc     + tig)*24 + g];
                uint32_t b1 = smu[OFF_SVN + (8*kc + 4 + tig)*24 + g];
                uint32_t c0 = smu[OFF_SVN + (8*kc     + tig)*24 + 8 + g];
                uint32_t c1 = smu[OFF_SVN + (8*kc + 4 + tig)*24 + 8 + g];
                mma8(S0,S1,S2,S3, ak.x,ak.y,ak.z,ak.w, b0,b1);
                mma8(S4,S5,S6,S7, ak.x,ak.y,ak.z,ak.w, c0,c1);
            }
            // tf32 copy of S for next step's L1
            uint2 p0, p1, p2, p3;
            p0.x = tf32r(S0); p0.y = tf32r(S1);
            p1.x = tf32r(S2); p1.y = tf32r(S3);
            p2.x = tf32r(S4); p2.y = tf32r(S5);
            p3.x = tf32r(S6); p3.y = tf32r(S7);
            *(uint2*)&smu[OFF_SS + (16*w + g    )*24 +     2*tig] = p0;
            *(uint2*)&smu[OFF_SS + (16*w + g + 8)*24 +     2*tig] = p1;
            *(uint2*)&smu[OFF_SS + (16*w + g    )*24 + 8 + 2*tig] = p2;
            *(uint2*)&smu[OFF_SS + (16*w + g + 8)*24 + 8 + 2*tig] = p3;
        }
        // loop-top barrier orders sS stores vs next L1 reads
    }

    if (write_sf) {
        float* base = out + OSZ + ((size_t)bh*DKD)*DVD + vb;
        *(float2*)(base + (16*w + g    )*DVD +     2*tig) = make_float2(S0, S1);
        *(float2*)(base + (16*w + g + 8)*DVD +     2*tig) = make_float2(S2, S3);
        *(float2*)(base + (16*w + g    )*DVD + 8 + 2*tig) = make_float2(S4, S5);
        *(float2*)(base + (16*w + g + 8)*DVD + 8 + 2*tig) = make_float2(S6, S7);
    }
}

// ---------------------------------------------------------------------------
extern "C" void kernel_launch(void* const* d_in, const int* in_sizes, int n_in,
                              void* d_out, int out_size)
{
    const float* q    = (const float*)d_in[0];
    const float* k    = (const float*)d_in[1];
    const float* v    = (const float*)d_in[2];
    const float* g    = (const float*)d_in[3];
    const float* beta = (const float*)d_in[4];
    float* out = (float*)d_out;

    cudaFuncSetAttribute(p1_kernel, cudaFuncAttributeMaxDynamicSharedMemorySize, P1_SMEM);
    cudaFuncSetAttribute(p2_kernel, cudaFuncAttributeMaxDynamicSharedMemorySize, P2_SMEM);

    p1_kernel<<<NCHUNKS, 256, P1_SMEM>>>(q, k, v, g, beta);

    int wsf = (out_size > OSZ) ? 1 : 0;
    p2_kernel<<<BHT*8, 256, P2_SMEM>>>(out, wsf);
}

// round 5
// speedup vs baseline: 2.4893x; 1.0282x over previous
#include <cuda_runtime.h>
#include <cstdint>

// Problem constants (fixed by setup_inputs)
#define SEQ  8192
#define DKD  128
#define DVD  128
#define BT   64
#define NCH  128          // SEQ/BT
#define BHT  16           // BB*HHD
#define NCHUNKS 2048      // BHT*NCH
#define OSZ  16777216     // BHT*SEQ*DVD  (size of o)

typedef unsigned long long u64;

// ---- tf32 helpers ----
__device__ __forceinline__ uint32_t tf32r(float f) {
    uint32_t u; asm("cvt.rna.tf32.f32 %0,%1;" : "=r"(u) : "f"(f)); return u;
}
__device__ __forceinline__ void mma8(float& d0, float& d1, float& d2, float& d3,
    uint32_t a0, uint32_t a1, uint32_t a2, uint32_t a3, uint32_t b0, uint32_t b1) {
    asm("mma.sync.aligned.m16n8k8.row.col.f32.tf32.tf32.f32 "
        "{%0,%1,%2,%3},{%4,%5,%6,%7},{%8,%9},{%0,%1,%2,%3};"
        : "+f"(d0), "+f"(d1), "+f"(d2), "+f"(d3)
        : "r"(a0), "r"(a1), "r"(a2), "r"(a3), "r"(b0), "r"(b1));
}

// ---- packed f32x2 helpers (p1 matmul) ----
__device__ __forceinline__ u64 pk2(float v) {
    u64 r; asm("mov.b64 %0,{%1,%1};" : "=l"(r) : "f"(v)); return r;
}
__device__ __forceinline__ u64 fma2(u64 a, u64 b, u64 c) {
    u64 d; asm("fma.rn.f32x2 %0,%1,%2,%3;" : "=l"(d) : "l"(a), "l"(b), "l"(c)); return d;
}
__device__ __forceinline__ float2 up2(u64 a) {
    float2 f; asm("mov.b64 {%0,%1},%2;" : "=f"(f.x), "=f"(f.y) : "l"(a)); return f;
}

// Scratch (device globals; tf32 bit patterns in uint32)
// Fragment-major layouts: element (block b, lane l, reg j) at [b*128 + l*4 + j].
__device__ uint32_t g_wf [NCHUNKS*8192];   // -w    : blocks b=(i>>4)*16+(c>>3)
__device__ uint32_t g_qef[NCHUNKS*8192];   // qe    : same block layout
__device__ uint32_t g_krf[NCHUNKS*8192];   // krT   : blocks b=(c>>4)*8+(i>>3)
__device__ uint32_t g_Af [NCHUNKS*4096];   // Aqk   : blocks b=(i>>4)*8+(j>>3)
__device__ float    g_u  [BHT*SEQ*DVD];    // u fp32 [row][V]
__device__ float    g_egl[NCHUNKS];

#define P1_SMEM ((8704*2 + 4352*2 + 3*64)*4)

// ---------------------------------------------------------------------------
// Phase 1: per-chunk (2048 CTAs). fp32 throughout; emits tf32 fragment tiles.
// ---------------------------------------------------------------------------
__global__ void __launch_bounds__(256, 2) p1_kernel(
    const float* __restrict__ q, const float* __restrict__ k,
    const float* __restrict__ v, const float* __restrict__ g,
    const float* __restrict__ beta)
{
    extern __shared__ float sm[];
    float* skT = sm;                 // [128][68] k transposed (normalized)
    float* sqT = skT + 8704;         // [128][68] q transposed; later: -w staged
    float* sA0 = sqT + 8704;         // [64][68]  strictly-lower A0
    float* sAq = sA0 + 4352;         // [64][68]  full Aqk
    float* seg = sAq + 4352;         // [64] exp(cumsum g)
    float* sie = seg + 64;           // [64] 1/seg
    float* sb  = sie + 64;           // [64] beta
    __shared__ float sgr[BT];

    const int cid = blockIdx.x;
    const int bh  = cid / NCH, n = cid % NCH;
    const int rowbase = bh*SEQ + n*BT;
    const int t = threadIdx.x;
    const int lane = t & 31, wid = t >> 5;

    if (t < BT) { sb[t] = beta[rowbase + t]; sgr[t] = g[rowbase + t]; }
    __syncthreads();
    if (t == 0) {
        float run = 0.f;
        for (int i = 0; i < BT; i++) {
            run += sgr[i];
            float e = expf(run);
            seg[i] = e; sie[i] = 1.f / e;
        }
        g_egl[cid] = seg[BT-1];
    }
    // normalize rows of q,k; store transposed
    for (int r = wid; r < BT; r += 8) {
        const float* kp = k + (size_t)(rowbase + r)*DKD;
        const float* qp = q + (size_t)(rowbase + r)*DKD;
        float k0=kp[lane],k1=kp[lane+32],k2=kp[lane+64],k3=kp[lane+96];
        float q0=qp[lane],q1=qp[lane+32],q2=qp[lane+64],q3=qp[lane+96];
        float ssk = k0*k0+k1*k1+k2*k2+k3*k3;
        float ssq = q0*q0+q1*q1+q2*q2+q3*q3;
        #pragma unroll
        for (int o = 16; o; o >>= 1) {
            ssk += __shfl_xor_sync(0xffffffffu, ssk, o);
            ssq += __shfl_xor_sync(0xffffffffu, ssq, o);
        }
        float ik = 1.f/(sqrtf(ssk)+1e-6f);
        float iq = 0.08838834764831845f/(sqrtf(ssq)+1e-6f);  // K^-0.5 folded in
        skT[(lane    )*68+r]=k0*ik; skT[(lane+32)*68+r]=k1*ik;
        skT[(lane+64)*68+r]=k2*ik; skT[(lane+96)*68+r]=k3*ik;
        sqT[(lane    )*68+r]=q0*iq; sqT[(lane+32)*68+r]=q1*iq;
        sqT[(lane+64)*68+r]=q2*iq; sqT[(lane+96)*68+r]=q3*iq;
    }
    __syncthreads();

    // Fused A0 (k·k^T) + Aqk (q·k^T): 4x4 register tiles, packed f32x2
    const int ty4 = (t >> 4)*4, tx4 = (t & 15)*4;
    u64 aK01[4], aK23[4], aQ01[4], aQ23[4];
    #pragma unroll
    for (int z = 0; z < 4; z++) { aK01[z]=0ull; aK23[z]=0ull; aQ01[z]=0ull; aQ23[z]=0ull; }
    #pragma unroll 4
    for (int kk = 0; kk < DKD; kk++) {
        const float* rk = skT + kk*68;
        ulonglong2 b   = *(const ulonglong2*)(rk + tx4);
        float4 kv4 = *(const float4*)(rk + ty4);
        float4 qv4 = *(const float4*)(sqT + kk*68 + ty4);
        float kvs[4] = {kv4.x,kv4.y,kv4.z,kv4.w};
        float qvs[4] = {qv4.x,qv4.y,qv4.z,qv4.w};
        #pragma unroll
        for (int ii = 0; ii < 4; ii++) {
            u64 kp2 = pk2(kvs[ii]), qp2 = pk2(qvs[ii]);
            aK01[ii] = fma2(kp2, b.x, aK01[ii]);
            aK23[ii] = fma2(kp2, b.y, aK23[ii]);
            aQ01[ii] = fma2(qp2, b.x, aQ01[ii]);
            aQ23[ii] = fma2(qp2, b.y, aQ23[ii]);
        }
    }
    #pragma unroll
    for (int ii = 0; ii < 4; ii++) {
        int i = ty4 + ii;
        float segi = seg[i], bi = sb[i];
        float2 ka = up2(aK01[ii]), kb = up2(aK23[ii]);
        float2 qa = up2(aQ01[ii]), qb = up2(aQ23[ii]);
        float aKv[4] = {ka.x,ka.y,kb.x,kb.y};
        float aQv[4] = {qa.x,qa.y,qb.x,qb.y};
        #pragma unroll
        for (int jj = 0; jj < 4; jj++) {
            int j = tx4 + jj;
            float rat = segi * sie[j];        // exp(gc_i - gc_j)
            if (j < i) sA0[i*68+j] = aKv[jj]*rat*bi;
            float f = (j < i) ? rat : ((j == i) ? 1.f : 0.f);
            sAq[i*68+j] = aQv[jj]*f;
        }
    }
    __syncthreads();

    // ---- Fragment emits (coalesced STG.128) ----
    // qe: blocks b = br*16+kc; a0=(i0,c0), a1=(i0+8,c0), a2=(i0,c0+4), a3=(i0+8,c0+4)
    for (int task = t; task < 2048; task += 256) {
        int b = task >> 5, l = task & 31;
        int br = b >> 4, kc = b & 15;
        int i0 = 16*br + (l>>2), c0 = 8*kc + (l&3);
        uint4 o;
        o.x = tf32r(sqT[(c0  )*68 + i0  ] * seg[i0  ]);
        o.y = tf32r(sqT[(c0  )*68 + i0+8] * seg[i0+8]);
        o.z = tf32r(sqT[(c0+4)*68 + i0  ] * seg[i0  ]);
        o.w = tf32r(sqT[(c0+4)*68 + i0+8] * seg[i0+8]);
        *(uint4*)&g_qef[(size_t)cid*8192 + b*128 + l*4] = o;
    }
    // krT: blocks b = cr*8+kc (c = state row / M, i = chunk row / K)
    {
        float egl2 = seg[BT-1];
        for (int task = t; task < 2048; task += 256) {
            int b = task >> 5, l = task & 31;
            int cr = b >> 3, kc = b & 7;
            int c0 = 16*cr + (l>>2), i0 = 8*kc + (l&3);
            uint4 o;
            o.x = tf32r(skT[(c0  )*68 + i0  ] * egl2 * sie[i0  ]);
            o.y = tf32r(skT[(c0+8)*68 + i0  ] * egl2 * sie[i0  ]);
            o.z = tf32r(skT[(c0  )*68 + i0+4] * egl2 * sie[i0+4]);
            o.w = tf32r(skT[(c0+8)*68 + i0+4] * egl2 * sie[i0+4]);
            *(uint4*)&g_krf[(size_t)cid*8192 + b*128 + l*4] = o;
        }
    }
    // Aqk: blocks b = br*8+kc
    for (int task = t; task < 1024; task += 256) {
        int b = task >> 5, l = task & 31;
        int br = b >> 3, kc = b & 7;
        int i0 = 16*br + (l>>2), j0 = 8*kc + (l&3);
        uint4 o;
        o.x = tf32r(sAq[(i0  )*68 + j0  ]);
        o.y = tf32r(sAq[(i0+8)*68 + j0  ]);
        o.z = tf32r(sAq[(i0  )*68 + j0+4]);
        o.w = tf32r(sAq[(i0+8)*68 + j0+4]);
        *(uint4*)&g_Af[(size_t)cid*4096 + b*128 + l*4] = o;
    }
    __syncthreads();   // emits done before solve overwrites sqT

    // Unit-lower triangular solve: t<128 k-cols -> stage -w into sqT; t>=128 v-cols -> u
    {
        float x[64];
        if (t < 128) {
            #pragma unroll
            for (int i = 0; i < 64; i++) x[i] = sb[i]*skT[t*68+i]*seg[i];
        } else {
            const float* vp = v + (size_t)rowbase*DVD + (t - 128);
            #pragma unroll
            for (int i = 0; i < 64; i++) x[i] = sb[i]*vp[i*DVD];
        }
        #pragma unroll
        for (int i = 1; i < 64; i++) {
            float s0 = 0.f, s1 = 0.f, s2 = 0.f, s3 = 0.f;
            int j = 0;
            #pragma unroll
            for (; j + 4 <= i; j += 4) {
                float4 a4 = *(const float4*)&sA0[i*68+j];
                s0 += a4.x*x[j]; s1 += a4.y*x[j+1];
                s2 += a4.z*x[j+2]; s3 += a4.w*x[j+3];
            }
            #pragma unroll
            for (; j < i; j++) s0 += sA0[i*68+j]*x[j];
            x[i] -= (s0 + s1) + (s2 + s3);
        }
        if (t < 128) {
            #pragma unroll
            for (int i = 0; i < 64; i++) sqT[t*68+i] = -x[i];   // stage NEGATED w
        } else {
            #pragma unroll
            for (int i = 0; i < 64; i++)
                g_u[(size_t)(rowbase+i)*DVD + (t-128)] = x[i];
        }
    }
    __syncthreads();

    // -w fragment emit (same block layout as qe)
    for (int task = t; task < 2048; task += 256) {
        int b = task >> 5, l = task & 31;
        int br = b >> 4, kc = b & 15;
        int i0 = 16*br + (l>>2), c0 = 8*kc + (l&3);
        uint4 o;
        o.x = tf32r(sqT[(c0  )*68 + i0  ]);
        o.y = tf32r(sqT[(c0  )*68 + i0+8]);
        o.z = tf32r(sqT[(c0+4)*68 + i0  ]);
        o.w = tf32r(sqT[(c0+4)*68 + i0+8]);
        *(uint4*)&g_wf[(size_t)cid*8192 + b*128 + l*4] = o;
    }
}

// ---------------------------------------------------------------------------
// Phase 2: state recurrence on tf32 mma.sync, A-operands direct from global.
// 128 CTAs (16 bh x 8 V-slices), 256 threads:
//   warps 0-3 ("v-warps"): L1 v = u + (-w)@S  ->  L3 S = egl*S + krT@v_new
//   warps 4-7 ("o-warps"): L1 o = qe@S        ->  L2 o += Aqk@v_new, store o
// Only B operands (sS, svn) live in smem (conflict-free stride-24).
// ---------------------------------------------------------------------------
__global__ void __launch_bounds__(256, 1) p2_kernel(float* __restrict__ out, int write_sf)
{
    __shared__ uint32_t sS [128*24];   // S tf32 mirror   [row][col16 pad24]
    __shared__ uint32_t svn[64*24];    // v_new tf32      [row][col16 pad24]
    __shared__ float    segl[NCH];

    const int t = threadIdx.x;
    const int w = t >> 5, l = t & 31, g = l >> 2, tig = l & 3;
    const int mr = w & 3;              // m-tile (rows 16*mr..) for L1/L2; strip 32*mr for L3
    const bool isv = (w < 4);
    const int bh = blockIdx.x >> 3;
    const int vb = (blockIdx.x & 7) * 16;

    for (int i = t; i < 128*24; i += 256) sS[i] = 0u;
    if (t < NCH) segl[t] = g_egl[bh*NCH + t];

    // persistent S (fp32), v-warps only: strip rows 32*mr..32*mr+31, cols 0..15
    // S[mt*8 + nt*4 + j]: mt in {0,1}, nt in {0,1}, j: c0..c3 fragment order
    float S[16];
    #pragma unroll
    for (int i = 0; i < 16; i++) S[i] = 0.f;

    const uint32_t* aL1 = (isv ? g_wf : g_qef);

    for (int n = 0; n < NCH; n++) {
        const int cid = bh*NCH + n;
        const size_t rb = (size_t)bh*SEQ + (size_t)n*BT;
        __syncthreads();   // orders prev-step sS/svn writes vs this step's reads

        // ---- L1 A fragments: 16 LDG.128 (deep MLP, L2-resident) ----
        const uint4* Ab = (const uint4*)(aL1 + (size_t)cid*8192) + mr*512 + l;
        uint4 A[16];
        #pragma unroll
        for (int kc = 0; kc < 16; kc++) A[kc] = Ab[kc*32];

        // accumulators: e = even-kc chain (init u for v-warps), o = odd-kc chain
        float e0,e1,e2,e3,e4,e5,e6,e7;
        float q0=0.f,q1=0.f,q2=0.f,q3=0.f,q4=0.f,q5=0.f,q6=0.f,q7=0.f;
        if (isv) {
            const float* up = g_u + (rb + 16*mr + g)*DVD + vb;
            float2 u00 = *(const float2*)(up + 2*tig);
            float2 u01 = *(const float2*)(up + 8 + 2*tig);
            float2 u10 = *(const float2*)(up + 8*DVD + 2*tig);
            float2 u11 = *(const float2*)(up + 8*DVD + 8 + 2*tig);
            e0=u00.x; e1=u00.y; e2=u10.x; e3=u10.y;
            e4=u01.x; e5=u01.y; e6=u11.x; e7=u11.y;
        } else {
            e0=e1=e2=e3=e4=e5=e6=e7=0.f;
        }

        #pragma unroll
        for (int kc = 0; kc < 16; kc++) {
            uint32_t b00 = sS[(8*kc     + tig)*24 + g];
            uint32_t b01 = sS[(8*kc + 4 + tig)*24 + g];
            uint32_t b10 = sS[(8*kc     + tig)*24 + 8 + g];
            uint32_t b11 = sS[(8*kc + 4 + tig)*24 + 8 + g];
            if (kc & 1) {
                mma8(q0,q1,q2,q3, A[kc].x,A[kc].y,A[kc].z,A[kc].w, b00,b01);
                mma8(q4,q5,q6,q7, A[kc].x,A[kc].y,A[kc].z,A[kc].w, b10,b11);
            } else {
                mma8(e0,e1,e2,e3, A[kc].x,A[kc].y,A[kc].z,A[kc].w, b00,b01);
                mma8(e4,e5,e6,e7, A[kc].x,A[kc].y,A[kc].z,A[kc].w, b10,b11);
            }
        }

        // ---- issue phase-2 A LDGs now (latency hides across barrier) ----
        uint4 K0[8], K1[8];   // v-warps: krf for m-tiles 2mr, 2mr+1
        uint4 AF[8];          // o-warps: Af for m-tile mr
        if (isv) {
            const uint4* Kb = (const uint4*)(g_krf + (size_t)cid*8192) + l;
            #pragma unroll
            for (int kc = 0; kc < 8; kc++) {
                K0[kc] = Kb[((2*mr    )*8 + kc)*32];
                K1[kc] = Kb[((2*mr + 1)*8 + kc)*32];
            }
        } else {
            const uint4* Fb = (const uint4*)(g_Af + (size_t)cid*4096) + mr*256 + l;
            #pragma unroll
            for (int kc = 0; kc < 8; kc++) AF[kc] = Fb[kc*32];
        }

        // combine chains
        float r0=e0+q0, r1=e1+q1, r2=e2+q2, r3=e3+q3;
        float r4=e4+q4, r5=e5+q5, r6=e6+q6, r7=e7+q7;

        if (isv) {
            // store v_new (tf32) rows 16mr+g (+8), cols nt*8+2tig (+1)
            uint2 p;
            p.x = tf32r(r0); p.y = tf32r(r1);
            *(uint2*)&svn[(16*mr + g    )*24 +     2*tig] = p;
            p.x = tf32r(r2); p.y = tf32r(r3);
            *(uint2*)&svn[(16*mr + g + 8)*24 +     2*tig] = p;
            p.x = tf32r(r4); p.y = tf32r(r5);
            *(uint2*)&svn[(16*mr + g    )*24 + 8 + 2*tig] = p;
            p.x = tf32r(r6); p.y = tf32r(r7);
            *(uint2*)&svn[(16*mr + g + 8)*24 + 8 + 2*tig] = p;
        }
        __syncthreads();   // svn published

        if (isv) {
            // ---- L3: D = krT @ v_new ; S = egl*S + D ----
            float D[16];
            #pragma unroll
            for (int i = 0; i < 16; i++) D[i] = 0.f;
            #pragma unroll
            for (int kc = 0; kc < 8; kc++) {
                uint32_t b00 = svn[(8*kc     + tig)*24 + g];
                uint32_t b01 = svn[(8*kc + 4 + tig)*24 + g];
                uint32_t b10 = svn[(8*kc     + tig)*24 + 8 + g];
                uint32_t b11 = svn[(8*kc + 4 + tig)*24 + 8 + g];
                mma8(D[0], D[1], D[2], D[3],  K0[kc].x,K0[kc].y,K0[kc].z,K0[kc].w, b00,b01);
                mma8(D[4], D[5], D[6], D[7],  K0[kc].x,K0[kc].y,K0[kc].z,K0[kc].w, b10,b11);
                mma8(D[8], D[9], D[10],D[11], K1[kc].x,K1[kc].y,K1[kc].z,K1[kc].w, b00,b01);
                mma8(D[12],D[13],D[14],D[15], K1[kc].x,K1[kc].y,K1[kc].z,K1[kc].w, b10,b11);
            }
            const float egl = segl[n];
            #pragma unroll
            for (int i = 0; i < 16; i++) S[i] = fmaf(egl, S[i], D[i]);

            // publish tf32 S mirror
            #pragma unroll
            for (int mt = 0; mt < 2; mt++) {
                int row0 = 32*mr + 16*mt + g;
                #pragma unroll
                for (int nt = 0; nt < 2; nt++) {
                    const float* sp = S + mt*8 + nt*4;
                    uint2 p;
                    p.x = tf32r(sp[0]); p.y = tf32r(sp[1]);
                    *(uint2*)&sS[(row0    )*24 + nt*8 + 2*tig] = p;
                    p.x = tf32r(sp[2]); p.y = tf32r(sp[3]);
                    *(uint2*)&sS[(row0 + 8)*24 + nt*8 + 2*tig] = p;
                }
            }
        } else {
            // ---- L2: o += Aqk @ v_new, then store o ----
            #pragma unroll
            for (int kc = 0; kc < 8; kc++) {
                uint32_t b00 = svn[(8*kc     + tig)*24 + g];
                uint32_t b01 = svn[(8*kc + 4 + tig)*24 + g];
                uint32_t b10 = svn[(8*kc     + tig)*24 + 8 + g];
                uint32_t b11 = svn[(8*kc + 4 + tig)*24 + 8 + g];
                mma8(r0,r1,r2,r3, AF[kc].x,AF[kc].y,AF[kc].z,AF[kc].w, b00,b01);
                mma8(r4,r5,r6,r7, AF[kc].x,AF[kc].y,AF[kc].z,AF[kc].w, b10,b11);
            }
            float* d0 = out + (rb + 16*mr + g)*DVD + vb;
            float* d1 = d0 + 8*DVD;
            *(float2*)(d0 +     2*tig) = make_float2(r0, r1);
            *(float2*)(d1 +     2*tig) = make_float2(r2, r3);
            *(float2*)(d0 + 8 + 2*tig) = make_float2(r4, r5);
            *(float2*)(d1 + 8 + 2*tig) = make_float2(r6, r7);
        }
    }

    if (write_sf && isv) {
        float* base = out + OSZ + (size_t)bh*DKD*DVD + vb;
        #pragma unroll
        for (int mt = 0; mt < 2; mt++) {
            int row0 = 32*mr + 16*mt + g;
            #pragma unroll
            for (int nt = 0; nt < 2; nt++) {
                const float* sp = S + mt*8 + nt*4;
                *(float2*)(base + (size_t)(row0    )*DVD + nt*8 + 2*tig) = make_float2(sp[0], sp[1]);
                *(float2*)(base + (size_t)(row0 + 8)*DVD + nt*8 + 2*tig) = make_float2(sp[2], sp[3]);
            }
        }
    }
}

// ---------------------------------------------------------------------------
extern "C" void kernel_launch(void* const* d_in, const int* in_sizes, int n_in,
                              void* d_out, int out_size)
{
    const float* q    = (const float*)d_in[0];
    const float* k    = (const float*)d_in[1];
    const float* v    = (const float*)d_in[2];
    const float* g    = (const float*)d_in[3];
    const float* beta = (const float*)d_in[4];
    float* out = (float*)d_out;

    cudaFuncSetAttribute(p1_kernel, cudaFuncAttributeMaxDynamicSharedMemorySize, P1_SMEM);

    p1_kernel<<<NCHUNKS, 256, P1_SMEM>>>(q, k, v, g, beta);

    int wsf = (out_size > OSZ) ? 1 : 0;
    p2_kernel<<<BHT*8, 256>>>(out, wsf);
}

// round 6
// speedup vs baseline: 2.5892x; 1.0402x over previous
#include <cuda_runtime.h>
#include <cstdint>

// Problem constants (fixed by setup_inputs)
#define SEQ  8192
#define DKD  128
#define DVD  128
#define BT   64
#define NCH  128          // SEQ/BT
#define BHT  16           // BB*HHD
#define NCHUNKS 2048      // BHT*NCH
#define OSZ  16777216     // BHT*SEQ*DVD  (size of o)

typedef unsigned long long u64;

// ---- tf32 helpers ----
__device__ __forceinline__ uint32_t tf32r(float f) {
    uint32_t u; asm("cvt.rna.tf32.f32 %0,%1;" : "=r"(u) : "f"(f)); return u;
}
__device__ __forceinline__ void mma8(float& d0, float& d1, float& d2, float& d3,
    uint32_t a0, uint32_t a1, uint32_t a2, uint32_t a3, uint32_t b0, uint32_t b1) {
    asm("mma.sync.aligned.m16n8k8.row.col.f32.tf32.tf32.f32 "
        "{%0,%1,%2,%3},{%4,%5,%6,%7},{%8,%9},{%0,%1,%2,%3};"
        : "+f"(d0), "+f"(d1), "+f"(d2), "+f"(d3)
        : "r"(a0), "r"(a1), "r"(a2), "r"(a3), "r"(b0), "r"(b1));
}

// ---- packed f32x2 helpers (p1 matmul) ----
__device__ __forceinline__ u64 pk2(float v) {
    u64 r; asm("mov.b64 %0,{%1,%1};" : "=l"(r) : "f"(v)); return r;
}
__device__ __forceinline__ u64 fma2(u64 a, u64 b, u64 c) {
    u64 d; asm("fma.rn.f32x2 %0,%1,%2,%3;" : "=l"(d) : "l"(a), "l"(b), "l"(c)); return d;
}
__device__ __forceinline__ float2 up2(u64 a) {
    float2 f; asm("mov.b64 {%0,%1},%2;" : "=f"(f.x), "=f"(f.y) : "l"(a)); return f;
}

// Scratch (device globals; tf32 bit patterns in uint32)
// Fragment-major layouts: element (block b, lane l, reg j) at [b*128 + l*4 + j].
__device__ uint32_t g_wf [NCHUNKS*8192];   // -w    : blocks b=(i>>4)*16+(c>>3)
__device__ uint32_t g_qef[NCHUNKS*8192];   // qe    : same block layout
__device__ uint32_t g_krf[NCHUNKS*8192];   // krT   : blocks b=(c>>4)*8+(i>>3)
__device__ uint32_t g_Af [NCHUNKS*4096];   // Aqk   : blocks b=(i>>4)*8+(j>>3)
__device__ float    g_u  [BHT*SEQ*DVD];    // u fp32 [row][V]
__device__ float    g_egl[NCHUNKS];

#define P1_SMEM ((8704*2 + 4352*2 + 3*64)*4)

// ---------------------------------------------------------------------------
// Phase 1: per-chunk (2048 CTAs). fp32 throughout; emits tf32 fragment tiles.
// ---------------------------------------------------------------------------
__global__ void __launch_bounds__(256, 2) p1_kernel(
    const float* __restrict__ q, const float* __restrict__ k,
    const float* __restrict__ v, const float* __restrict__ g,
    const float* __restrict__ beta)
{
    extern __shared__ float sm[];
    float* skT = sm;                 // [128][68] k transposed (normalized)
    float* sqT = skT + 8704;         // [128][68] q transposed; later: -w staged
    float* sA0 = sqT + 8704;         // [64][68]  strictly-lower A0
    float* sAq = sA0 + 4352;         // [64][68]  full Aqk
    float* seg = sAq + 4352;         // [64] exp(cumsum g)
    float* sie = seg + 64;           // [64] 1/seg
    float* sb  = sie + 64;           // [64] beta
    __shared__ float sgr[BT];

    const int cid = blockIdx.x;
    const int bh  = cid / NCH, n = cid % NCH;
    const int rowbase = bh*SEQ + n*BT;
    const int t = threadIdx.x;
    const int lane = t & 31, wid = t >> 5;

    if (t < BT) { sb[t] = beta[rowbase + t]; sgr[t] = g[rowbase + t]; }
    __syncthreads();
    // parallel cumsum + exp on warp 0 (2 elements per lane, warp scan)
    if (t < 32) {
        float a = sgr[2*t], b = sgr[2*t+1];
        float s = a + b;
        #pragma unroll
        for (int o = 1; o < 32; o <<= 1) {
            float y = __shfl_up_sync(0xffffffffu, s, o);
            if (t >= o) s += y;
        }
        float gc1 = s;         // cumsum through 2t+1
        float gc0 = s - b;     // cumsum through 2t
        seg[2*t  ] = __expf(gc0);  sie[2*t  ] = __expf(-gc0);
        seg[2*t+1] = __expf(gc1);  sie[2*t+1] = __expf(-gc1);
        if (t == 31) g_egl[cid] = seg[63];
    }
    // normalize rows of q,k; store transposed
    for (int r = wid; r < BT; r += 8) {
        const float* kp = k + (size_t)(rowbase + r)*DKD;
        const float* qp = q + (size_t)(rowbase + r)*DKD;
        float k0=kp[lane],k1=kp[lane+32],k2=kp[lane+64],k3=kp[lane+96];
        float q0=qp[lane],q1=qp[lane+32],q2=qp[lane+64],q3=qp[lane+96];
        float ssk = k0*k0+k1*k1+k2*k2+k3*k3;
        float ssq = q0*q0+q1*q1+q2*q2+q3*q3;
        #pragma unroll
        for (int o = 16; o; o >>= 1) {
            ssk += __shfl_xor_sync(0xffffffffu, ssk, o);
            ssq += __shfl_xor_sync(0xffffffffu, ssq, o);
        }
        float ik = 1.f/(sqrtf(ssk)+1e-6f);
        float iq = 0.08838834764831845f/(sqrtf(ssq)+1e-6f);  // K^-0.5 folded in
        skT[(lane    )*68+r]=k0*ik; skT[(lane+32)*68+r]=k1*ik;
        skT[(lane+64)*68+r]=k2*ik; skT[(lane+96)*68+r]=k3*ik;
        sqT[(lane    )*68+r]=q0*iq; sqT[(lane+32)*68+r]=q1*iq;
        sqT[(lane+64)*68+r]=q2*iq; sqT[(lane+96)*68+r]=q3*iq;
    }
    __syncthreads();

    // Fused A0 (k·k^T) + Aqk (q·k^T): 4x4 register tiles, packed f32x2
    const int ty4 = (t >> 4)*4, tx4 = (t & 15)*4;
    u64 aK01[4], aK23[4], aQ01[4], aQ23[4];
    #pragma unroll
    for (int z = 0; z < 4; z++) { aK01[z]=0ull; aK23[z]=0ull; aQ01[z]=0ull; aQ23[z]=0ull; }
    #pragma unroll 4
    for (int kk = 0; kk < DKD; kk++) {
        const float* rk = skT + kk*68;
        ulonglong2 b   = *(const ulonglong2*)(rk + tx4);
        float4 kv4 = *(const float4*)(rk + ty4);
        float4 qv4 = *(const float4*)(sqT + kk*68 + ty4);
        float kvs[4] = {kv4.x,kv4.y,kv4.z,kv4.w};
        float qvs[4] = {qv4.x,qv4.y,qv4.z,qv4.w};
        #pragma unroll
        for (int ii = 0; ii < 4; ii++) {
            u64 kp2 = pk2(kvs[ii]), qp2 = pk2(qvs[ii]);
            aK01[ii] = fma2(kp2, b.x, aK01[ii]);
            aK23[ii] = fma2(kp2, b.y, aK23[ii]);
            aQ01[ii] = fma2(qp2, b.x, aQ01[ii]);
            aQ23[ii] = fma2(qp2, b.y, aQ23[ii]);
        }
    }
    #pragma unroll
    for (int ii = 0; ii < 4; ii++) {
        int i = ty4 + ii;
        float segi = seg[i], bi = sb[i];
        float2 ka = up2(aK01[ii]), kb = up2(aK23[ii]);
        float2 qa = up2(aQ01[ii]), qb = up2(aQ23[ii]);
        float aKv[4] = {ka.x,ka.y,kb.x,kb.y};
        float aQv[4] = {qa.x,qa.y,qb.x,qb.y};
        #pragma unroll
        for (int jj = 0; jj < 4; jj++) {
            int j = tx4 + jj;
            float rat = segi * sie[j];        // exp(gc_i - gc_j)
            if (j < i) sA0[i*68+j] = aKv[jj]*rat*bi;
            float f = (j < i) ? rat : ((j == i) ? 1.f : 0.f);
            sAq[i*68+j] = aQv[jj]*f;
        }
    }
    __syncthreads();

    // ---- Fragment emits (coalesced STG.128) ----
    for (int task = t; task < 2048; task += 256) {
        int b = task >> 5, l = task & 31;
        int br = b >> 4, kc = b & 15;
        int i0 = 16*br + (l>>2), c0 = 8*kc + (l&3);
        uint4 o;
        o.x = tf32r(sqT[(c0  )*68 + i0  ] * seg[i0  ]);
        o.y = tf32r(sqT[(c0  )*68 + i0+8] * seg[i0+8]);
        o.z = tf32r(sqT[(c0+4)*68 + i0  ] * seg[i0  ]);
        o.w = tf32r(sqT[(c0+4)*68 + i0+8] * seg[i0+8]);
        *(uint4*)&g_qef[(size_t)cid*8192 + b*128 + l*4] = o;
    }
    {
        float egl2 = seg[BT-1];
        for (int task = t; task < 2048; task += 256) {
            int b = task >> 5, l = task & 31;
            int cr = b >> 3, kc = b & 7;
            int c0 = 16*cr + (l>>2), i0 = 8*kc + (l&3);
            uint4 o;
            o.x = tf32r(skT[(c0  )*68 + i0  ] * egl2 * sie[i0  ]);
            o.y = tf32r(skT[(c0+8)*68 + i0  ] * egl2 * sie[i0  ]);
            o.z = tf32r(skT[(c0  )*68 + i0+4] * egl2 * sie[i0+4]);
            o.w = tf32r(skT[(c0+8)*68 + i0+4] * egl2 * sie[i0+4]);
            *(uint4*)&g_krf[(size_t)cid*8192 + b*128 + l*4] = o;
        }
    }
    for (int task = t; task < 1024; task += 256) {
        int b = task >> 5, l = task & 31;
        int br = b >> 3, kc = b & 7;
        int i0 = 16*br + (l>>2), j0 = 8*kc + (l&3);
        uint4 o;
        o.x = tf32r(sAq[(i0  )*68 + j0  ]);
        o.y = tf32r(sAq[(i0+8)*68 + j0  ]);
        o.z = tf32r(sAq[(i0  )*68 + j0+4]);
        o.w = tf32r(sAq[(i0+8)*68 + j0+4]);
        *(uint4*)&g_Af[(size_t)cid*4096 + b*128 + l*4] = o;
    }
    __syncthreads();   // emits done before solve overwrites sqT

    // Unit-lower triangular solve
    {
        float x[64];
        if (t < 128) {
            #pragma unroll
            for (int i = 0; i < 64; i++) x[i] = sb[i]*skT[t*68+i]*seg[i];
        } else {
            const float* vp = v + (size_t)rowbase*DVD + (t - 128);
            #pragma unroll
            for (int i = 0; i < 64; i++) x[i] = sb[i]*vp[i*DVD];
        }
        #pragma unroll
        for (int i = 1; i < 64; i++) {
            float s0 = 0.f, s1 = 0.f, s2 = 0.f, s3 = 0.f;
            int j = 0;
            #pragma unroll
            for (; j + 4 <= i; j += 4) {
                float4 a4 = *(const float4*)&sA0[i*68+j];
                s0 += a4.x*x[j]; s1 += a4.y*x[j+1];
                s2 += a4.z*x[j+2]; s3 += a4.w*x[j+3];
            }
            #pragma unroll
            for (; j < i; j++) s0 += sA0[i*68+j]*x[j];
            x[i] -= (s0 + s1) + (s2 + s3);
        }
        if (t < 128) {
            #pragma unroll
            for (int i = 0; i < 64; i++) sqT[t*68+i] = -x[i];   // stage NEGATED w
        } else {
            #pragma unroll
            for (int i = 0; i < 64; i++)
                g_u[(size_t)(rowbase+i)*DVD + (t-128)] = x[i];
        }
    }
    __syncthreads();

    // -w fragment emit (same block layout as qe)
    for (int task = t; task < 2048; task += 256) {
        int b = task >> 5, l = task & 31;
        int br = b >> 4, kc = b & 15;
        int i0 = 16*br + (l>>2), c0 = 8*kc + (l&3);
        uint4 o;
        o.x = tf32r(sqT[(c0  )*68 + i0  ]);
        o.y = tf32r(sqT[(c0  )*68 + i0+8]);
        o.z = tf32r(sqT[(c0+4)*68 + i0  ]);
        o.w = tf32r(sqT[(c0+4)*68 + i0+8]);
        *(uint4*)&g_wf[(size_t)cid*8192 + b*128 + l*4] = o;
    }
}

// ---------------------------------------------------------------------------
// Phase 2: state recurrence on tf32 mma.sync. 128 CTAs, 512 threads/16 warps.
//   v-warps 0-7 : (mr=w>>1, kh=w&1) K-split of L1 v=u+(-w)@S; L3 owns 16-row S strip
//   o-warps 8-15: (mr,kh)            K-split of L1 o=qe@S and L2 o+=Aqk@v_new
// A-operands direct LDG.128 from global (L2-resident), prefetched a step ahead.
// ---------------------------------------------------------------------------
__global__ void __launch_bounds__(512, 1) p2_kernel(float* __restrict__ out, int write_sf)
{
    __shared__ uint32_t sS [128*24];   // S tf32 mirror [row][col16 pad24]
    __shared__ uint32_t svn[64*24];    // v_new tf32
    __shared__ float    sPv[1024];     // v partials [mr][lane][8]
    __shared__ float    sPo[1024];     // o partials
    __shared__ float    segl[NCH];

    const int t = threadIdx.x;
    const int w = t >> 5, l = t & 31, g = l >> 2, tig = l & 3;
    const bool isv = (w < 8);
    const int w2 = isv ? w : (w - 8);
    const int mr = w2 >> 1, kh = w2 & 1;
    const int bh = blockIdx.x >> 3;
    const int vb = (blockIdx.x & 7) * 16;

    for (int i = t; i < 128*24; i += 512) sS[i] = 0u;
    if (t < NCH) segl[t] = g_egl[bh*NCH + t];
    __syncthreads();

    // persistent S (v-warps): strip rows 16w..16w+15, cols 0..15 -> 8 regs
    float S0=0.f,S1=0.f,S2=0.f,S3=0.f,S4=0.f,S5=0.f,S6=0.f,S7=0.f;

    const uint32_t* aL1base = isv ? g_wf : g_qef;

    // initial L1-A prefetch (n=0)
    uint4 A[8];
    {
        const uint4* Ab = (const uint4*)(aL1base + (size_t)(bh*NCH)*8192)
                        + (mr*16 + kh*8)*32 + l;
        #pragma unroll
        for (int j = 0; j < 8; j++) A[j] = Ab[j*32];
    }

    for (int n = 0; n < NCH; n++) {
        const int cid = bh*NCH + n;
        const size_t rb = (size_t)bh*SEQ + (size_t)n*BT;

        // issue this step's L3 K loads (consumed after B2)
        uint4 K[8];
        if (isv) {
            const uint4* Kb = (const uint4*)(g_krf + (size_t)cid*8192) + (w*8)*32 + l;
            #pragma unroll
            for (int j = 0; j < 8; j++) K[j] = Kb[j*32];
        }
        // u loads (v kh0, consumed after B1)
        float2 u00, u01, u10, u11;
        if (isv && kh == 0) {
            const float* up = g_u + (rb + 16*mr + g)*DVD + vb;
            u00 = *(const float2*)(up + 2*tig);
            u01 = *(const float2*)(up + 8 + 2*tig);
            u10 = *(const float2*)(up + 8*DVD + 2*tig);
            u11 = *(const float2*)(up + 8*DVD + 8 + 2*tig);
        }

        // ---- L1 partial: kc = kh*8 + j, j=0..7 vs sS
        float e0=0.f,e1=0.f,e2=0.f,e3=0.f,e4=0.f,e5=0.f,e6=0.f,e7=0.f;
        #pragma unroll
        for (int j = 0; j < 8; j++) {
            int kc = kh*8 + j;
            uint32_t b00 = sS[(8*kc     + tig)*24 + g];
            uint32_t b01 = sS[(8*kc + 4 + tig)*24 + g];
            uint32_t b10 = sS[(8*kc     + tig)*24 + 8 + g];
            uint32_t b11 = sS[(8*kc + 4 + tig)*24 + 8 + g];
            mma8(e0,e1,e2,e3, A[j].x,A[j].y,A[j].z,A[j].w, b00,b01);
            mma8(e4,e5,e6,e7, A[j].x,A[j].y,A[j].z,A[j].w, b10,b11);
        }

        // ---- prefetch next step's L1 A (regs now dead)
        if (n + 1 < NCH) {
            const uint4* Ab = (const uint4*)(aL1base + (size_t)(cid+1)*8192)
                            + (mr*16 + kh*8)*32 + l;
            #pragma unroll
            for (int j = 0; j < 8; j++) A[j] = Ab[j*32];
        }
        // ---- o-warps: load this step's Aqk quarter (consumed after B2)
        uint4 AF[4];
        if (!isv) {
            const uint4* Fb = (const uint4*)(g_Af + (size_t)cid*4096)
                            + (mr*8 + kh*4)*32 + l;
            #pragma unroll
            for (int j = 0; j < 4; j++) AF[j] = Fb[j*32];
        }
        // ---- v kh1 publishes L1 partials
        if (isv && kh == 1) {
            float* p = sPv + mr*256 + l*8;
            *(float4*)p     = make_float4(e0,e1,e2,e3);
            *(float4*)(p+4) = make_float4(e4,e5,e6,e7);
        }
        __syncthreads();   // B1

        // ---- v kh0: combine partials + u -> v_new (tf32) into svn
        if (isv && kh == 0) {
            const float* p = sPv + mr*256 + l*8;
            float4 pa = *(const float4*)p, pb = *(const float4*)(p+4);
            float v0 = e0+pa.x+u00.x, v1 = e1+pa.y+u00.y;
            float v2 = e2+pa.z+u10.x, v3 = e3+pa.w+u10.y;
            float v4 = e4+pb.x+u01.x, v5 = e5+pb.y+u01.y;
            float v6 = e6+pb.z+u11.x, v7 = e7+pb.w+u11.y;
            uint2 q;
            q.x=tf32r(v0); q.y=tf32r(v1); *(uint2*)&svn[(16*mr+g    )*24 +     2*tig] = q;
            q.x=tf32r(v2); q.y=tf32r(v3); *(uint2*)&svn[(16*mr+g + 8)*24 +     2*tig] = q;
            q.x=tf32r(v4); q.y=tf32r(v5); *(uint2*)&svn[(16*mr+g    )*24 + 8 + 2*tig] = q;
            q.x=tf32r(v6); q.y=tf32r(v7); *(uint2*)&svn[(16*mr+g + 8)*24 + 8 + 2*tig] = q;
        }
        __syncthreads();   // B2

        if (isv) {
            // ---- L3: S = egl*S + krT @ v_new (strip rows 16w..16w+15, K=64)
            const float egl = segl[n];
            S0*=egl; S1*=egl; S2*=egl; S3*=egl; S4*=egl; S5*=egl; S6*=egl; S7*=egl;
            #pragma unroll
            for (int kc = 0; kc < 8; kc++) {
                uint32_t b00 = svn[(8*kc     + tig)*24 + g];
                uint32_t b01 = svn[(8*kc + 4 + tig)*24 + g];
                uint32_t b10 = svn[(8*kc     + tig)*24 + 8 + g];
                uint32_t b11 = svn[(8*kc + 4 + tig)*24 + 8 + g];
                mma8(S0,S1,S2,S3, K[kc].x,K[kc].y,K[kc].z,K[kc].w, b00,b01);
                mma8(S4,S5,S6,S7, K[kc].x,K[kc].y,K[kc].z,K[kc].w, b10,b11);
            }
            // publish tf32 S mirror
            uint2 q;
            q.x=tf32r(S0); q.y=tf32r(S1); *(uint2*)&sS[(16*w+g    )*24 +     2*tig] = q;
            q.x=tf32r(S2); q.y=tf32r(S3); *(uint2*)&sS[(16*w+g + 8)*24 +     2*tig] = q;
            q.x=tf32r(S4); q.y=tf32r(S5); *(uint2*)&sS[(16*w+g    )*24 + 8 + 2*tig] = q;
            q.x=tf32r(S6); q.y=tf32r(S7); *(uint2*)&sS[(16*w+g + 8)*24 + 8 + 2*tig] = q;
        } else {
            // ---- L2 partial: kc = kh*4 + j over v_new (K=64 split)
            #pragma unroll
            for (int j = 0; j < 4; j++) {
                int kc = kh*4 + j;
                uint32_t b00 = svn[(8*kc     + tig)*24 + g];
                uint32_t b01 = svn[(8*kc + 4 + tig)*24 + g];
                uint32_t b10 = svn[(8*kc     + tig)*24 + 8 + g];
                uint32_t b11 = svn[(8*kc + 4 + tig)*24 + 8 + g];
                mma8(e0,e1,e2,e3, AF[j].x,AF[j].y,AF[j].z,AF[j].w, b00,b01);
                mma8(e4,e5,e6,e7, AF[j].x,AF[j].y,AF[j].z,AF[j].w, b10,b11);
            }
            if (kh == 1) {
                float* p = sPo + mr*256 + l*8;
                *(float4*)p     = make_float4(e0,e1,e2,e3);
                *(float4*)(p+4) = make_float4(e4,e5,e6,e7);
            }
        }
        __syncthreads();   // B3 (sS + o-partials published)

        // ---- o kh0: combine and store o (overlaps next step's LDG/mma)
        if (!isv && kh == 0) {
            const float* p = sPo + mr*256 + l*8;
            float4 pa = *(const float4*)p, pb = *(const float4*)(p+4);
            float* d0 = out + (rb + 16*mr + g)*DVD + vb;
            float* d1 = d0 + 8*DVD;
            *(float2*)(d0 +     2*tig) = make_float2(e0+pa.x, e1+pa.y);
            *(float2*)(d1 +     2*tig) = make_float2(e2+pa.z, e3+pa.w);
            *(float2*)(d0 + 8 + 2*tig) = make_float2(e4+pb.x, e5+pb.y);
            *(float2*)(d1 + 8 + 2*tig) = make_float2(e6+pb.z, e7+pb.w);
        }
    }

    if (write_sf && isv) {
        float* base = out + OSZ + (size_t)bh*DKD*DVD + vb;
        int row0 = 16*w + g;
        *(float2*)(base + (size_t)(row0    )*DVD +     2*tig) = make_float2(S0, S1);
        *(float2*)(base + (size_t)(row0 + 8)*DVD +     2*tig) = make_float2(S2, S3);
        *(float2*)(base + (size_t)(row0    )*DVD + 8 + 2*tig) = make_float2(S4, S5);
        *(float2*)(base + (size_t)(row0 + 8)*DVD + 8 + 2*tig) = make_float2(S6, S7);
    }
}

// ---------------------------------------------------------------------------
extern "C" void kernel_launch(void* const* d_in, const int* in_sizes, int n_in,
                              void* d_out, int out_size)
{
    const float* q    = (const float*)d_in[0];
    const float* k    = (const float*)d_in[1];
    const float* v    = (const float*)d_in[2];
    const float* g    = (const float*)d_in[3];
    const float* beta = (const float*)d_in[4];
    float* out = (float*)d_out;

    cudaFuncSetAttribute(p1_kernel, cudaFuncAttributeMaxDynamicSharedMemorySize, P1_SMEM);

    p1_kernel<<<NCHUNKS, 256, P1_SMEM>>>(q, k, v, g, beta);

    int wsf = (out_size > OSZ) ? 1 : 0;
    p2_kernel<<<BHT*8, 512>>>(out, wsf);
}

// round 7
// speedup vs baseline: 2.8413x; 1.0973x over previous
#include <cuda_runtime.h>
#include <cuda_fp16.h>
#include <cstdint>

// Problem constants (fixed by setup_inputs)
#define SEQ  8192
#define DKD  128
#define DVD  128
#define BT   64
#define NCH  128          // SEQ/BT
#define BHT  16           // BB*HHD
#define NCHUNKS 2048      // BHT*NCH
#define OSZ  16777216     // BHT*SEQ*DVD  (size of o)

typedef unsigned long long u64;

// ---- fp16 helpers ----
__device__ __forceinline__ uint32_t h2(float lo, float hi) {
    __half2 h = __floats2half2_rn(lo, hi);
    return *reinterpret_cast<uint32_t*>(&h);
}
__device__ __forceinline__ void mma16(float& d0, float& d1, float& d2, float& d3,
    uint32_t a0, uint32_t a1, uint32_t a2, uint32_t a3, uint32_t b0, uint32_t b1) {
    asm("mma.sync.aligned.m16n8k16.row.col.f32.f16.f16.f32 "
        "{%0,%1,%2,%3},{%4,%5,%6,%7},{%8,%9},{%0,%1,%2,%3};"
        : "+f"(d0), "+f"(d1), "+f"(d2), "+f"(d3)
        : "r"(a0), "r"(a1), "r"(a2), "r"(a3), "r"(b0), "r"(b1));
}

// ---- packed f32x2 helpers (p1 matmul) ----
__device__ __forceinline__ u64 pk2(float v) {
    u64 r; asm("mov.b64 %0,{%1,%1};" : "=l"(r) : "f"(v)); return r;
}
__device__ __forceinline__ u64 fma2(u64 a, u64 b, u64 c) {
    u64 d; asm("fma.rn.f32x2 %0,%1,%2,%3;" : "=l"(d) : "l"(a), "l"(b), "l"(c)); return d;
}
__device__ __forceinline__ float2 up2(u64 a) {
    float2 f; asm("mov.b64 {%0,%1},%2;" : "=f"(f.x), "=f"(f.y) : "l"(a)); return f;
}

// Scratch (device globals; fp16 fragment-major, half2 packed along K)
// A-fragment word j for lane l: j0=(i0,k0|k0+1) j1=(i0+8,k0) j2=(i0,k0+8) j3=(i0+8,k0+8)
__device__ uint32_t g_wfh [NCHUNKS*4096];  // -w   64x128: block b = mr*8 + kc(8)
__device__ uint32_t g_qefh[NCHUNKS*4096];  // qe   64x128: same blocks
__device__ uint32_t g_krfh[NCHUNKS*4096];  // krT 128x64 : block b = cr*4 + kc(4)
__device__ uint32_t g_Afh [NCHUNKS*2048];  // Aqk  64x64 : block b = mr*4 + kc(4)
__device__ __half   g_uh  [BHT*SEQ*DVD];   // u fp16 [row][V]
__device__ float    g_egl [NCHUNKS];

#define P1_SMEM ((8704*2 + 4352*2 + 3*64)*4)

// ---------------------------------------------------------------------------
// Phase 1: per-chunk (2048 CTAs). fp32 compute; emits fp16 fragment tiles.
// ---------------------------------------------------------------------------
__global__ void __launch_bounds__(256, 2) p1_kernel(
    const float* __restrict__ q, const float* __restrict__ k,
    const float* __restrict__ v, const float* __restrict__ g,
    const float* __restrict__ beta)
{
    extern __shared__ float sm[];
    float* skT = sm;                 // [128][68] k transposed (normalized)
    float* sqT = skT + 8704;         // [128][68] q transposed; later: -w staged
    float* sA0 = sqT + 8704;         // [64][68]  strictly-lower A0
    float* sAq = sA0 + 4352;         // [64][68]  full Aqk
    float* seg = sAq + 4352;         // [64] exp(cumsum g)
    float* sie = seg + 64;           // [64] 1/seg
    float* sb  = sie + 64;           // [64] beta
    __shared__ float sgr[BT];

    const int cid = blockIdx.x;
    const int bh  = cid / NCH, n = cid % NCH;
    const int rowbase = bh*SEQ + n*BT;
    const int t = threadIdx.x;
    const int lane = t & 31, wid = t >> 5;

    if (t < BT) { sb[t] = beta[rowbase + t]; sgr[t] = g[rowbase + t]; }
    __syncthreads();
    // parallel cumsum + exp on warp 0 (2 elements per lane, warp scan)
    if (t < 32) {
        float a = sgr[2*t], b = sgr[2*t+1];
        float s = a + b;
        #pragma unroll
        for (int o = 1; o < 32; o <<= 1) {
            float y = __shfl_up_sync(0xffffffffu, s, o);
            if (t >= o) s += y;
        }
        float gc1 = s;
        float gc0 = s - b;
        seg[2*t  ] = __expf(gc0);  sie[2*t  ] = __expf(-gc0);
        seg[2*t+1] = __expf(gc1);  sie[2*t+1] = __expf(-gc1);
        if (t == 31) g_egl[cid] = seg[63];
    }
    // normalize rows of q,k; store transposed
    for (int r = wid; r < BT; r += 8) {
        const float* kp = k + (size_t)(rowbase + r)*DKD;
        const float* qp = q + (size_t)(rowbase + r)*DKD;
        float k0=kp[lane],k1=kp[lane+32],k2=kp[lane+64],k3=kp[lane+96];
        float q0=qp[lane],q1=qp[lane+32],q2=qp[lane+64],q3=qp[lane+96];
        float ssk = k0*k0+k1*k1+k2*k2+k3*k3;
        float ssq = q0*q0+q1*q1+q2*q2+q3*q3;
        #pragma unroll
        for (int o = 16; o; o >>= 1) {
            ssk += __shfl_xor_sync(0xffffffffu, ssk, o);
            ssq += __shfl_xor_sync(0xffffffffu, ssq, o);
        }
        float ik = 1.f/(sqrtf(ssk)+1e-6f);
        float iq = 0.08838834764831845f/(sqrtf(ssq)+1e-6f);  // K^-0.5 folded in
        skT[(lane    )*68+r]=k0*ik; skT[(lane+32)*68+r]=k1*ik;
        skT[(lane+64)*68+r]=k2*ik; skT[(lane+96)*68+r]=k3*ik;
        sqT[(lane    )*68+r]=q0*iq; sqT[(lane+32)*68+r]=q1*iq;
        sqT[(lane+64)*68+r]=q2*iq; sqT[(lane+96)*68+r]=q3*iq;
    }
    __syncthreads();

    // Fused A0 (k·k^T) + Aqk (q·k^T): 4x4 register tiles, packed f32x2
    const int ty4 = (t >> 4)*4, tx4 = (t & 15)*4;
    u64 aK01[4], aK23[4], aQ01[4], aQ23[4];
    #pragma unroll
    for (int z = 0; z < 4; z++) { aK01[z]=0ull; aK23[z]=0ull; aQ01[z]=0ull; aQ23[z]=0ull; }
    #pragma unroll 4
    for (int kk = 0; kk < DKD; kk++) {
        const float* rk = skT + kk*68;
        ulonglong2 b   = *(const ulonglong2*)(rk + tx4);
        float4 kv4 = *(const float4*)(rk + ty4);
        float4 qv4 = *(const float4*)(sqT + kk*68 + ty4);
        float kvs[4] = {kv4.x,kv4.y,kv4.z,kv4.w};
        float qvs[4] = {qv4.x,qv4.y,qv4.z,qv4.w};
        #pragma unroll
        for (int ii = 0; ii < 4; ii++) {
            u64 kp2 = pk2(kvs[ii]), qp2 = pk2(qvs[ii]);
            aK01[ii] = fma2(kp2, b.x, aK01[ii]);
            aK23[ii] = fma2(kp2, b.y, aK23[ii]);
            aQ01[ii] = fma2(qp2, b.x, aQ01[ii]);
            aQ23[ii] = fma2(qp2, b.y, aQ23[ii]);
        }
    }
    #pragma unroll
    for (int ii = 0; ii < 4; ii++) {
        int i = ty4 + ii;
        float segi = seg[i], bi = sb[i];
        float2 ka = up2(aK01[ii]), kb = up2(aK23[ii]);
        float2 qa = up2(aQ01[ii]), qb = up2(aQ23[ii]);
        float aKv[4] = {ka.x,ka.y,kb.x,kb.y};
        float aQv[4] = {qa.x,qa.y,qb.x,qb.y};
        #pragma unroll
        for (int jj = 0; jj < 4; jj++) {
            int j = tx4 + jj;
            float rat = segi * sie[j];        // exp(gc_i - gc_j)
            if (j < i) sA0[i*68+j] = aKv[jj]*rat*bi;
            float f = (j < i) ? rat : ((j == i) ? 1.f : 0.f);
            sAq[i*68+j] = aQv[jj]*f;
        }
    }
    __syncthreads();

    // ---- fp16 fragment emits (coalesced STG.128) ----
    // qe 64x128: M[i][c] = sqT[c*68+i]*seg[i]; blocks b = mr*8+kc
    for (int task = t; task < 1024; task += 256) {
        int b = task >> 5, l = task & 31;
        int i0 = 16*(b>>3) + (l>>2), k0 = 16*(b&7) + (l&3)*2;
        float s0 = seg[i0], s1 = seg[i0+8];
        uint4 o;
        o.x = h2(sqT[(k0  )*68+i0  ]*s0, sqT[(k0+1)*68+i0  ]*s0);
        o.y = h2(sqT[(k0  )*68+i0+8]*s1, sqT[(k0+1)*68+i0+8]*s1);
        o.z = h2(sqT[(k0+8)*68+i0  ]*s0, sqT[(k0+9)*68+i0  ]*s0);
        o.w = h2(sqT[(k0+8)*68+i0+8]*s1, sqT[(k0+9)*68+i0+8]*s1);
        *(uint4*)&g_qefh[(size_t)cid*4096 + b*128 + l*4] = o;
    }
    // krT 128x64: M[c][i] = skT[c*68+i]*egl*sie[i]; blocks b = cr*4+kc
    {
        float egl2 = seg[BT-1];
        for (int task = t; task < 1024; task += 256) {
            int b = task >> 5, l = task & 31;
            int c0 = 16*(b>>2) + (l>>2), i0 = 16*(b&3) + (l&3)*2;
            float e0 = egl2*sie[i0], e1 = egl2*sie[i0+1];
            float e8 = egl2*sie[i0+8], e9 = egl2*sie[i0+9];
            uint4 o;
            o.x = h2(skT[(c0  )*68+i0  ]*e0, skT[(c0  )*68+i0+1]*e1);
            o.y = h2(skT[(c0+8)*68+i0  ]*e0, skT[(c0+8)*68+i0+1]*e1);
            o.z = h2(skT[(c0  )*68+i0+8]*e8, skT[(c0  )*68+i0+9]*e9);
            o.w = h2(skT[(c0+8)*68+i0+8]*e8, skT[(c0+8)*68+i0+9]*e9);
            *(uint4*)&g_krfh[(size_t)cid*4096 + b*128 + l*4] = o;
        }
    }
    // Aqk 64x64: blocks b = mr*4+kc
    for (int task = t; task < 512; task += 256) {
        int b = task >> 5, l = task & 31;
        int i0 = 16*(b>>2) + (l>>2), j0 = 16*(b&3) + (l&3)*2;
        uint4 o;
        o.x = h2(sAq[(i0  )*68+j0  ], sAq[(i0  )*68+j0+1]);
        o.y = h2(sAq[(i0+8)*68+j0  ], sAq[(i0+8)*68+j0+1]);
        o.z = h2(sAq[(i0  )*68+j0+8], sAq[(i0  )*68+j0+9]);
        o.w = h2(sAq[(i0+8)*68+j0+8], sAq[(i0+8)*68+j0+9]);
        *(uint4*)&g_Afh[(size_t)cid*2048 + b*128 + l*4] = o;
    }
    __syncthreads();   // emits done before solve overwrites sqT

    // Unit-lower triangular solve
    {
        float x[64];
        if (t < 128) {
            #pragma unroll
            for (int i = 0; i < 64; i++) x[i] = sb[i]*skT[t*68+i]*seg[i];
        } else {
            const float* vp = v + (size_t)rowbase*DVD + (t - 128);
            #pragma unroll
            for (int i = 0; i < 64; i++) x[i] = sb[i]*vp[i*DVD];
        }
        #pragma unroll
        for (int i = 1; i < 64; i++) {
            float s0 = 0.f, s1 = 0.f, s2 = 0.f, s3 = 0.f;
            int j = 0;
            #pragma unroll
            for (; j + 4 <= i; j += 4) {
                float4 a4 = *(const float4*)&sA0[i*68+j];
                s0 += a4.x*x[j]; s1 += a4.y*x[j+1];
                s2 += a4.z*x[j+2]; s3 += a4.w*x[j+3];
            }
            #pragma unroll
            for (; j < i; j++) s0 += sA0[i*68+j]*x[j];
            x[i] -= (s0 + s1) + (s2 + s3);
        }
        if (t < 128) {
            #pragma unroll
            for (int i = 0; i < 64; i++) sqT[t*68+i] = -x[i];   // stage NEGATED w
        } else {
            #pragma unroll
            for (int i = 0; i < 64; i++)
                g_uh[(size_t)(rowbase+i)*DVD + (t-128)] = __float2half_rn(x[i]);
        }
    }
    __syncthreads();

    // -w fragment emit (layout like qe, no scaling)
    for (int task = t; task < 1024; task += 256) {
        int b = task >> 5, l = task & 31;
        int i0 = 16*(b>>3) + (l>>2), k0 = 16*(b&7) + (l&3)*2;
        uint4 o;
        o.x = h2(sqT[(k0  )*68+i0  ], sqT[(k0+1)*68+i0  ]);
        o.y = h2(sqT[(k0  )*68+i0+8], sqT[(k0+1)*68+i0+8]);
        o.z = h2(sqT[(k0+8)*68+i0  ], sqT[(k0+9)*68+i0  ]);
        o.w = h2(sqT[(k0+8)*68+i0+8], sqT[(k0+9)*68+i0+8]);
        *(uint4*)&g_wfh[(size_t)cid*4096 + b*128 + l*4] = o;
    }
}

// ---------------------------------------------------------------------------
// Phase 2: state recurrence on fp16 mma.sync (m16n8k16, fp32 accum).
// 128 CTAs (16 bh x 8 V-slices), 256 threads / 8 warps:
//   v-warps 0-3: L1 v=u+(-w)@S (m-tile mr, full K) -> L3 owns 32-row S strip
//   o-warps 4-7: L1 o=qe@S                          -> L2 o+=Aqk@v_new, store
// B operands in smem as half2 [n][pad][k-pair] (conflict-free). 2 barriers/step.
// ---------------------------------------------------------------------------
__global__ void __launch_bounds__(256, 1) p2_kernel(float* __restrict__ out, int write_sf)
{
    __shared__ uint32_t sS [16*68];   // S mirror: word n*68+p = half2(S[2p][n],S[2p+1][n])
    __shared__ uint32_t svn[16*36];   // v_new:    word n*36+p = half2(v[2p][n],v[2p+1][n])
    __shared__ float    segl[NCH];

    const int t = threadIdx.x;
    const int w = t >> 5, l = t & 31, g = l >> 2, tig = l & 3;
    const bool isv = (w < 4);
    const int mr = w & 3;
    const int bh = blockIdx.x >> 3;
    const int vb = (blockIdx.x & 7) * 16;

    __half* sSh  = reinterpret_cast<__half*>(sS);
    __half* svnh = reinterpret_cast<__half*>(svn);

    for (int i = t; i < 16*68; i += 256) sS[i] = 0u;
    if (t < NCH) segl[t] = g_egl[bh*NCH + t];
    __syncthreads();

    // persistent S (v-warps): strip rows 32mr..32mr+31, cols 0..15
    // S[mt*8 + nh*4 + j]; j: (r,c0),(r,c0+1),(r+8,c0),(r+8,c0+1)
    float S[16];
    #pragma unroll
    for (int i = 0; i < 16; i++) S[i] = 0.f;

    const uint32_t* aL1 = isv ? g_wfh : g_qefh;

    // initial L1-A prefetch (n=0): 8 blocks (full K=128)
    uint4 A[8];
    {
        const uint4* Ab = (const uint4*)(aL1 + (size_t)(bh*NCH)*4096) + (mr*8)*32 + l;
        #pragma unroll
        for (int j = 0; j < 8; j++) A[j] = Ab[j*32];
    }

    for (int n = 0; n < NCH; n++) {
        const int cid = bh*NCH + n;
        const size_t rb = (size_t)bh*SEQ + (size_t)n*BT;

        // this step's post-B1 A operands (issued early, consumed after B1)
        uint4 K[8];   // v: krT m-tiles 2mr, 2mr+1 (kc 0..3 each)
        uint4 AF[4];  // o: Aqk m-tile mr
        if (isv) {
            const uint4* Kb = (const uint4*)(g_krfh + (size_t)cid*4096) + l;
            #pragma unroll
            for (int mt = 0; mt < 2; mt++)
                #pragma unroll
                for (int kc = 0; kc < 4; kc++)
                    K[mt*4+kc] = Kb[(((2*mr+mt)*4 + kc))*32];
        } else {
            const uint4* Fb = (const uint4*)(g_Afh + (size_t)cid*2048) + (mr*4)*32 + l;
            #pragma unroll
            for (int kc = 0; kc < 4; kc++) AF[kc] = Fb[kc*32];
        }

        // accumulators (v: init from u; o: zero)
        float a0,a1,a2,a3,a4,a5,a6,a7;
        if (isv) {
            const __half2* u0 = (const __half2*)(g_uh + (size_t)(rb + 16*mr + g    )*DVD + vb);
            const __half2* u1 = (const __half2*)(g_uh + (size_t)(rb + 16*mr + g + 8)*DVD + vb);
            float2 u00 = __half22float2(u0[tig]);
            float2 u01 = __half22float2(u0[4+tig]);
            float2 u10 = __half22float2(u1[tig]);
            float2 u11 = __half22float2(u1[4+tig]);
            a0=u00.x; a1=u00.y; a2=u10.x; a3=u10.y;
            a4=u01.x; a5=u01.y; a6=u11.x; a7=u11.y;
        } else {
            a0=a1=a2=a3=a4=a5=a6=a7=0.f;
        }

        // ---- L1: full K=128 (8 k16-chunks), both n-halves per chunk
        #pragma unroll
        for (int kc = 0; kc < 8; kc++) {
            uint32_t b00 = sS[(g  )*68 + 8*kc     + tig];
            uint32_t b01 = sS[(g  )*68 + 8*kc + 4 + tig];
            uint32_t b10 = sS[(8+g)*68 + 8*kc     + tig];
            uint32_t b11 = sS[(8+g)*68 + 8*kc + 4 + tig];
            mma16(a0,a1,a2,a3, A[kc].x,A[kc].y,A[kc].z,A[kc].w, b00,b01);
            mma16(a4,a5,a6,a7, A[kc].x,A[kc].y,A[kc].z,A[kc].w, b10,b11);
        }

        // ---- prefetch next step's L1 A (regs dead)
        if (n + 1 < NCH) {
            const uint4* Ab = (const uint4*)(aL1 + (size_t)(cid+1)*4096) + (mr*8)*32 + l;
            #pragma unroll
            for (int j = 0; j < 8; j++) A[j] = Ab[j*32];
        }

        // ---- v: publish v_new (fp16 halves into [n][p] layout)
        if (isv) {
            int p0 = (16*mr + g) >> 1, hb = g & 1;
            svnh[((2*tig  )*36 + p0  )*2 + hb] = __float2half_rn(a0);
            svnh[((2*tig+1)*36 + p0  )*2 + hb] = __float2half_rn(a1);
            svnh[((2*tig  )*36 + p0+4)*2 + hb] = __float2half_rn(a2);
            svnh[((2*tig+1)*36 + p0+4)*2 + hb] = __float2half_rn(a3);
            svnh[((8+2*tig  )*36 + p0  )*2 + hb] = __float2half_rn(a4);
            svnh[((8+2*tig+1)*36 + p0  )*2 + hb] = __float2half_rn(a5);
            svnh[((8+2*tig  )*36 + p0+4)*2 + hb] = __float2half_rn(a6);
            svnh[((8+2*tig+1)*36 + p0+4)*2 + hb] = __float2half_rn(a7);
        }
        __syncthreads();   // B1: svn published; all sS reads done

        if (isv) {
            // ---- L3: S = egl*S + krT @ v_new (2 m-tiles x 2 n-halves, K=64)
            const float egl = segl[n];
            #pragma unroll
            for (int i = 0; i < 16; i++) S[i] *= egl;
            #pragma unroll
            for (int kc = 0; kc < 4; kc++) {
                uint32_t b00 = svn[(g  )*36 + 8*kc     + tig];
                uint32_t b01 = svn[(g  )*36 + 8*kc + 4 + tig];
                uint32_t b10 = svn[(8+g)*36 + 8*kc     + tig];
                uint32_t b11 = svn[(8+g)*36 + 8*kc + 4 + tig];
                mma16(S[0], S[1], S[2], S[3],  K[kc  ].x,K[kc  ].y,K[kc  ].z,K[kc  ].w, b00,b01);
                mma16(S[4], S[5], S[6], S[7],  K[kc  ].x,K[kc  ].y,K[kc  ].z,K[kc  ].w, b10,b11);
                mma16(S[8], S[9], S[10],S[11], K[4+kc].x,K[4+kc].y,K[4+kc].z,K[4+kc].w, b00,b01);
                mma16(S[12],S[13],S[14],S[15], K[4+kc].x,K[4+kc].y,K[4+kc].z,K[4+kc].w, b10,b11);
            }
            // publish fp16 S mirror
            #pragma unroll
            for (int mt = 0; mt < 2; mt++) {
                int r = 32*mr + 16*mt + g;
                int p = r >> 1, hb = r & 1;
                #pragma unroll
                for (int nh = 0; nh < 2; nh++) {
                    int c0 = nh*8 + 2*tig;
                    const float* sp = S + mt*8 + nh*4;
                    sSh[((c0  )*68 + p  )*2 + hb] = __float2half_rn(sp[0]);
                    sSh[((c0+1)*68 + p  )*2 + hb] = __float2half_rn(sp[1]);
                    sSh[((c0  )*68 + p+4)*2 + hb] = __float2half_rn(sp[2]);
                    sSh[((c0+1)*68 + p+4)*2 + hb] = __float2half_rn(sp[3]);
                }
            }
        } else {
            // ---- L2: o += Aqk @ v_new (K=64), then store o
            #pragma unroll
            for (int kc = 0; kc < 4; kc++) {
                uint32_t b00 = svn[(g  )*36 + 8*kc     + tig];
                uint32_t b01 = svn[(g  )*36 + 8*kc + 4 + tig];
                uint32_t b10 = svn[(8+g)*36 + 8*kc     + tig];
                uint32_t b11 = svn[(8+g)*36 + 8*kc + 4 + tig];
                mma16(a0,a1,a2,a3, AF[kc].x,AF[kc].y,AF[kc].z,AF[kc].w, b00,b01);
                mma16(a4,a5,a6,a7, AF[kc].x,AF[kc].y,AF[kc].z,AF[kc].w, b10,b11);
            }
            float* d0 = out + (rb + 16*mr + g)*DVD + vb;
            float* d1 = d0 + 8*DVD;
            *(float2*)(d0 +     2*tig) = make_float2(a0, a1);
            *(float2*)(d1 +     2*tig) = make_float2(a2, a3);
            *(float2*)(d0 + 8 + 2*tig) = make_float2(a4, a5);
            *(float2*)(d1 + 8 + 2*tig) = make_float2(a6, a7);
        }
        __syncthreads();   // B2: sS published; svn consumed
    }

    if (write_sf && isv) {
        float* base = out + OSZ + (size_t)bh*DKD*DVD + vb;
        #pragma unroll
        for (int mt = 0; mt < 2; mt++) {
            int r = 32*mr + 16*mt + g;
            #pragma unroll
            for (int nh = 0; nh < 2; nh++) {
                const float* sp = S + mt*8 + nh*4;
                *(float2*)(base + (size_t)(r    )*DVD + nh*8 + 2*tig) = make_float2(sp[0], sp[1]);
                *(float2*)(base + (size_t)(r + 8)*DVD + nh*8 + 2*tig) = make_float2(sp[2], sp[3]);
            }
        }
    }
}

// ---------------------------------------------------------------------------
extern "C" void kernel_launch(void* const* d_in, const int* in_sizes, int n_in,
                              void* d_out, int out_size)
{
    const float* q    = (const float*)d_in[0];
    const float* k    = (const float*)d_in[1];
    const float* v    = (const float*)d_in[2];
    const float* g    = (const float*)d_in[3];
    const float* beta = (const float*)d_in[4];
    float* out = (float*)d_out;

    cudaFuncSetAttribute(p1_kernel, cudaFuncAttributeMaxDynamicSharedMemorySize, P1_SMEM);

    p1_kernel<<<NCHUNKS, 256, P1_SMEM>>>(q, k, v, g, beta);

    int wsf = (out_size > OSZ) ? 1 : 0;
    p2_kernel<<<BHT*8, 256>>>(out, wsf);
}

// round 8
// speedup vs baseline: 3.6273x; 1.2766x over previous
#include <cuda_runtime.h>
#include <cuda_fp16.h>
#include <cstdint>

// Problem constants (fixed by setup_inputs)
#define SEQ  8192
#define DKD  128
#define DVD  128
#define BT   64
#define NCH  128          // SEQ/BT
#define BHT  16           // BB*HHD
#define NCHUNKS 2048      // BHT*NCH
#define OSZ  16777216     // BHT*SEQ*DVD  (size of o)

typedef unsigned long long u64;

// ---- fp16 helpers ----
__device__ __forceinline__ uint32_t h2(float lo, float hi) {
    __half2 h = __floats2half2_rn(lo, hi);
    return *reinterpret_cast<uint32_t*>(&h);
}
__device__ __forceinline__ void mma16(float& d0, float& d1, float& d2, float& d3,
    uint32_t a0, uint32_t a1, uint32_t a2, uint32_t a3, uint32_t b0, uint32_t b1) {
    asm("mma.sync.aligned.m16n8k16.row.col.f32.f16.f16.f32 "
        "{%0,%1,%2,%3},{%4,%5,%6,%7},{%8,%9},{%0,%1,%2,%3};"
        : "+f"(d0), "+f"(d1), "+f"(d2), "+f"(d3)
        : "r"(a0), "r"(a1), "r"(a2), "r"(a3), "r"(b0), "r"(b1));
}

// ---- packed f32x2 helpers (p1 A0 matmul) ----
__device__ __forceinline__ u64 pk2(float v) {
    u64 r; asm("mov.b64 %0,{%1,%1};" : "=l"(r) : "f"(v)); return r;
}
__device__ __forceinline__ u64 fma2(u64 a, u64 b, u64 c) {
    u64 d; asm("fma.rn.f32x2 %0,%1,%2,%3;" : "=l"(d) : "l"(a), "l"(b), "l"(c)); return d;
}
__device__ __forceinline__ float2 up2(u64 a) {
    float2 f; asm("mov.b64 {%0,%1},%2;" : "=f"(f.x), "=f"(f.y) : "l"(a)); return f;
}

// Scratch (device globals; fp16 fragment-major, half2 packed along K)
__device__ uint32_t g_wfh [NCHUNKS*4096];  // -w   64x128: block b = mr*8 + kc(8)
__device__ uint32_t g_qefh[NCHUNKS*4096];  // qe   64x128: same blocks
__device__ uint32_t g_krfh[NCHUNKS*4096];  // krT 128x64 : block b = cr*4 + kc(4)
__device__ uint32_t g_Afh [NCHUNKS*2048];  // Aqk  64x64 : block b = mr*4 + kc(4)
__device__ __half   g_uh  [BHT*SEQ*DVD];   // u fp16 [row][V]
__device__ float    g_egl [NCHUNKS];

#define P1_SMEM ((8704*2 + 4352 + 3*64)*4)

// ---------------------------------------------------------------------------
// Phase 1: per-chunk (2048 CTAs). A0 in fp32 (feeds solve); Aqk via fp16 mma
// emitted straight from registers; emits overlapped on the other warp-half.
// ---------------------------------------------------------------------------
__global__ void __launch_bounds__(256, 2) p1_kernel(
    const float* __restrict__ q, const float* __restrict__ k,
    const float* __restrict__ v, const float* __restrict__ g,
    const float* __restrict__ beta)
{
    extern __shared__ float sm[];
    float* skT = sm;                 // [128][68] k transposed (normalized)
    float* sqT = skT + 8704;         // [128][68] q transposed; later: -w staged
    float* sA0 = sqT + 8704;         // [64][68]  strictly-lower A0
    float* seg = sA0 + 4352;         // [64] exp(cumsum g)
    float* sie = seg + 64;           // [64] 1/seg
    float* sb  = sie + 64;           // [64] beta
    __shared__ float sgr[BT];

    const int cid = blockIdx.x;
    const int bh  = cid / NCH, n = cid % NCH;
    const int rowbase = bh*SEQ + n*BT;
    const int t = threadIdx.x;
    const int lane = t & 31, wid = t >> 5;
    const int gq = lane >> 2, tig = lane & 3;

    if (t < BT) { sb[t] = beta[rowbase + t]; sgr[t] = g[rowbase + t]; }
    __syncthreads();
    if (t < 32) {
        float a = sgr[2*t], b = sgr[2*t+1];
        float s = a + b;
        #pragma unroll
        for (int o = 1; o < 32; o <<= 1) {
            float y = __shfl_up_sync(0xffffffffu, s, o);
            if (t >= o) s += y;
        }
        float gc1 = s, gc0 = s - b;
        seg[2*t  ] = __expf(gc0);  sie[2*t  ] = __expf(-gc0);
        seg[2*t+1] = __expf(gc1);  sie[2*t+1] = __expf(-gc1);
        if (t == 31) g_egl[cid] = seg[63];
    }
    // normalize rows of q,k; store transposed
    for (int r = wid; r < BT; r += 8) {
        const float* kp = k + (size_t)(rowbase + r)*DKD;
        const float* qp = q + (size_t)(rowbase + r)*DKD;
        float k0=kp[lane],k1=kp[lane+32],k2=kp[lane+64],k3=kp[lane+96];
        float q0=qp[lane],q1=qp[lane+32],q2=qp[lane+64],q3=qp[lane+96];
        float ssk = k0*k0+k1*k1+k2*k2+k3*k3;
        float ssq = q0*q0+q1*q1+q2*q2+q3*q3;
        #pragma unroll
        for (int o = 16; o; o >>= 1) {
            ssk += __shfl_xor_sync(0xffffffffu, ssk, o);
            ssq += __shfl_xor_sync(0xffffffffu, ssq, o);
        }
        float ik = 1.f/(sqrtf(ssk)+1e-6f);
        float iq = 0.08838834764831845f/(sqrtf(ssq)+1e-6f);  // K^-0.5 folded in
        skT[(lane    )*68+r]=k0*ik; skT[(lane+32)*68+r]=k1*ik;
        skT[(lane+64)*68+r]=k2*ik; skT[(lane+96)*68+r]=k3*ik;
        sqT[(lane    )*68+r]=q0*iq; sqT[(lane+32)*68+r]=q1*iq;
        sqT[(lane+64)*68+r]=q2*iq; sqT[(lane+96)*68+r]=q3*iq;
    }
    __syncthreads();

    // ---- A0 = k·k^T (fp32 f32x2), 4x4 register tiles on 16x16 thread grid
    {
        const int ty4 = (t >> 4)*4, tx4 = (t & 15)*4;
        u64 aK01[4], aK23[4];
        #pragma unroll
        for (int z = 0; z < 4; z++) { aK01[z]=0ull; aK23[z]=0ull; }
        #pragma unroll 4
        for (int kk = 0; kk < DKD; kk++) {
            const float* rk = skT + kk*68;
            ulonglong2 b = *(const ulonglong2*)(rk + tx4);
            float4 kv4 = *(const float4*)(rk + ty4);
            float kvs[4] = {kv4.x,kv4.y,kv4.z,kv4.w};
            #pragma unroll
            for (int ii = 0; ii < 4; ii++) {
                u64 kp2 = pk2(kvs[ii]);
                aK01[ii] = fma2(kp2, b.x, aK01[ii]);
                aK23[ii] = fma2(kp2, b.y, aK23[ii]);
            }
        }
        #pragma unroll
        for (int ii = 0; ii < 4; ii++) {
            int i = ty4 + ii;
            float segi = seg[i], bi = sb[i];
            float2 ka = up2(aK01[ii]), kb = up2(aK23[ii]);
            float aKv[4] = {ka.x,ka.y,kb.x,kb.y};
            #pragma unroll
            for (int jj = 0; jj < 4; jj++) {
                int j = tx4 + jj;
                if (j < i) sA0[i*68+j] = aKv[jj]*(segi*sie[j])*bi;
            }
        }
    }

    // ---- warps 0-3: Aqk via fp16 mma, emit g_Afh from registers
    //      warps 4-7: krf + qef emits (read skT/sqT/seg/sie only)
    if (wid < 4) {
        const int mr = wid;
        const int i0 = 16*mr + gq, i8 = i0 + 8;
        float D[8][4];
        #pragma unroll
        for (int z = 0; z < 8; z++) { D[z][0]=0.f; D[z][1]=0.f; D[z][2]=0.f; D[z][3]=0.f; }
        #pragma unroll
        for (int kc = 0; kc < 8; kc++) {
            int kb = 16*kc;
            uint32_t a0 = h2(sqT[(kb+2*tig  )*68+i0], sqT[(kb+2*tig+1)*68+i0]);
            uint32_t a1 = h2(sqT[(kb+2*tig  )*68+i8], sqT[(kb+2*tig+1)*68+i8]);
            uint32_t a2 = h2(sqT[(kb+2*tig+8)*68+i0], sqT[(kb+2*tig+9)*68+i0]);
            uint32_t a3 = h2(sqT[(kb+2*tig+8)*68+i8], sqT[(kb+2*tig+9)*68+i8]);
            #pragma unroll
            for (int nt = 0; nt < 8; nt++) {
                int jn = 8*nt + gq;
                uint32_t b0 = h2(skT[(kb+2*tig  )*68+jn], skT[(kb+2*tig+1)*68+jn]);
                uint32_t b1 = h2(skT[(kb+2*tig+8)*68+jn], skT[(kb+2*tig+9)*68+jn]);
                mma16(D[nt][0],D[nt][1],D[nt][2],D[nt][3], a0,a1,a2,a3, b0,b1);
            }
        }
        float s_i0 = seg[i0], s_i8 = seg[i8];
        #pragma unroll
        for (int c = 0; c < 4; c++) {
            int j0 = 16*c + 2*tig;
            float f00 = (j0   < i0) ? s_i0*sie[j0  ] : ((j0  ==i0)?1.f:0.f);
            float f01 = (j0+1 < i0) ? s_i0*sie[j0+1] : ((j0+1==i0)?1.f:0.f);
            float f80 = (j0   < i8) ? s_i8*sie[j0  ] : ((j0  ==i8)?1.f:0.f);
            float f81 = (j0+1 < i8) ? s_i8*sie[j0+1] : ((j0+1==i8)?1.f:0.f);
            float h00 = (j0+8 < i0) ? s_i0*sie[j0+8] : ((j0+8==i0)?1.f:0.f);
            float h01 = (j0+9 < i0) ? s_i0*sie[j0+9] : ((j0+9==i0)?1.f:0.f);
            float h80 = (j0+8 < i8) ? s_i8*sie[j0+8] : ((j0+8==i8)?1.f:0.f);
            float h81 = (j0+9 < i8) ? s_i8*sie[j0+9] : ((j0+9==i8)?1.f:0.f);
            uint4 o;
            o.x = h2(D[2*c  ][0]*f00, D[2*c  ][1]*f01);
            o.y = h2(D[2*c  ][2]*f80, D[2*c  ][3]*f81);
            o.z = h2(D[2*c+1][0]*h00, D[2*c+1][1]*h01);
            o.w = h2(D[2*c+1][2]*h80, D[2*c+1][3]*h81);
            *(uint4*)&g_Afh[(size_t)cid*2048 + (mr*4+c)*128 + lane*4] = o;
        }
    } else {
        float egl2 = seg[BT-1];
        for (int task = t - 128; task < 1024; task += 128) {
            int b = task >> 5, l = task & 31;
            int c0 = 16*(b>>2) + (l>>2), i0 = 16*(b&3) + (l&3)*2;
            float e0 = egl2*sie[i0], e1 = egl2*sie[i0+1];
            float e8 = egl2*sie[i0+8], e9 = egl2*sie[i0+9];
            uint4 o;
            o.x = h2(skT[(c0  )*68+i0  ]*e0, skT[(c0  )*68+i0+1]*e1);
            o.y = h2(skT[(c0+8)*68+i0  ]*e0, skT[(c0+8)*68+i0+1]*e1);
            o.z = h2(skT[(c0  )*68+i0+8]*e8, skT[(c0  )*68+i0+9]*e9);
            o.w = h2(skT[(c0+8)*68+i0+8]*e8, skT[(c0+8)*68+i0+9]*e9);
            *(uint4*)&g_krfh[(size_t)cid*4096 + b*128 + l*4] = o;
        }
        for (int task = t - 128; task < 1024; task += 128) {
            int b = task >> 5, l = task & 31;
            int i0 = 16*(b>>3) + (l>>2), k0 = 16*(b&7) + (l&3)*2;
            float s0 = seg[i0], s1 = seg[i0+8];
            uint4 o;
            o.x = h2(sqT[(k0  )*68+i0  ]*s0, sqT[(k0+1)*68+i0  ]*s0);
            o.y = h2(sqT[(k0  )*68+i0+8]*s1, sqT[(k0+1)*68+i0+8]*s1);
            o.z = h2(sqT[(k0+8)*68+i0  ]*s0, sqT[(k0+9)*68+i0  ]*s0);
            o.w = h2(sqT[(k0+8)*68+i0+8]*s1, sqT[(k0+9)*68+i0+8]*s1);
            *(uint4*)&g_qefh[(size_t)cid*4096 + b*128 + l*4] = o;
        }
    }
    __syncthreads();   // sA0 ready; emits done before sqT is overwritten

    // Unit-lower triangular solve
    {
        float x[64];
        if (t < 128) {
            #pragma unroll
            for (int i = 0; i < 64; i++) x[i] = sb[i]*skT[t*68+i]*seg[i];
        } else {
            const float* vp = v + (size_t)rowbase*DVD + (t - 128);
            #pragma unroll
            for (int i = 0; i < 64; i++) x[i] = sb[i]*vp[i*DVD];
        }
        #pragma unroll
        for (int i = 1; i < 64; i++) {
            float s0 = 0.f, s1 = 0.f, s2 = 0.f, s3 = 0.f;
            int j = 0;
            #pragma unroll
            for (; j + 4 <= i; j += 4) {
                float4 a4 = *(const float4*)&sA0[i*68+j];
                s0 += a4.x*x[j]; s1 += a4.y*x[j+1];
                s2 += a4.z*x[j+2]; s3 += a4.w*x[j+3];
            }
            #pragma unroll
            for (; j < i; j++) s0 += sA0[i*68+j]*x[j];
            x[i] -= (s0 + s1) + (s2 + s3);
        }
        if (t < 128) {
            #pragma unroll
            for (int i = 0; i < 64; i++) sqT[t*68+i] = -x[i];   // stage NEGATED w
        } else {
            #pragma unroll
            for (int i = 0; i < 64; i++)
                g_uh[(size_t)(rowbase+i)*DVD + (t-128)] = __float2half_rn(x[i]);
        }
    }
    __syncthreads();

    // -w fragment emit (all 256 threads)
    for (int task = t; task < 1024; task += 256) {
        int b = task >> 5, l = task & 31;
        int i0 = 16*(b>>3) + (l>>2), k0 = 16*(b&7) + (l&3)*2;
        uint4 o;
        o.x = h2(sqT[(k0  )*68+i0  ], sqT[(k0+1)*68+i0  ]);
        o.y = h2(sqT[(k0  )*68+i0+8], sqT[(k0+1)*68+i0+8]);
        o.z = h2(sqT[(k0+8)*68+i0  ], sqT[(k0+9)*68+i0  ]);
        o.w = h2(sqT[(k0+8)*68+i0+8], sqT[(k0+9)*68+i0+8]);
        *(uint4*)&g_wfh[(size_t)cid*4096 + b*128 + l*4] = o;
    }
}

// ---------------------------------------------------------------------------
// Phase 2: fp16 mma recurrence, software-pipelined.
// Double-buffered sS/svn; ONE full barrier per step + a v-warps-only named
// barrier. o-warps run one step behind (carry qe@S partial + Aqk frags).
// ---------------------------------------------------------------------------
__global__ void __launch_bounds__(256, 1) p2_kernel(float* __restrict__ out, int write_sf)
{
    __shared__ uint32_t sSb [2][16*68];   // S mirror, double buffered
    __shared__ uint32_t svnb[2][16*36];   // v_new, double buffered
    __shared__ float    segl[NCH];

    const int t = threadIdx.x;
    const int w = t >> 5, l = t & 31, g = l >> 2, tig = l & 3;
    const bool isv = (w < 4);
    const int mr = w & 3;
    const int bh = blockIdx.x >> 3;
    const int vb = (blockIdx.x & 7) * 16;

    for (int i = t; i < 16*68; i += 256) sSb[0][i] = 0u;
    if (t < NCH) segl[t] = g_egl[bh*NCH + t];
    __syncthreads();

    float S[16];                       // v-warps: persistent fp32 state strip
    #pragma unroll
    for (int i = 0; i < 16; i++) S[i] = 0.f;
    float C[8];                        // o-warps: carried o accumulator
    uint4 AF[4];                       // o-warps: carried Aqk frags (prev step)
    uint4 A[8];                        // L1 A frags (prefetched)
    uint4 K[8];                        // v-warps: krT frags (prefetched)
    uint32_t ur[4];                    // v-warps: u half2 regs (prefetched)

    const uint32_t* aL1 = isv ? g_wfh : g_qefh;
    {
        const uint4* Ab = (const uint4*)(aL1 + (size_t)(bh*NCH)*4096) + (mr*8)*32 + l;
        #pragma unroll
        for (int j = 0; j < 8; j++) A[j] = Ab[j*32];
        if (isv) {
            const uint4* Kb = (const uint4*)(g_krfh + (size_t)(bh*NCH)*4096) + l;
            #pragma unroll
            for (int mt = 0; mt < 2; mt++)
                #pragma unroll
                for (int kc = 0; kc < 4; kc++)
                    K[mt*4+kc] = Kb[((2*mr+mt)*4 + kc)*32];
            const uint32_t* up = (const uint32_t*)(g_uh + (size_t)(bh*SEQ + 16*mr + g)*DVD + vb);
            ur[0] = up[tig]; ur[1] = up[4+tig];
            ur[2] = up[512+tig]; ur[3] = up[512+4+tig];
        }
    }

    for (int n = 0; n < NCH; n++) {
        const int cid = bh*NCH + n;
        const size_t rb = (size_t)bh*SEQ + (size_t)n*BT;
        const int cur = n & 1;
        uint32_t* sSr  = sSb[cur];
        uint32_t* sSw  = sSb[cur^1];
        uint32_t* svnw = svnb[cur];
        uint32_t* svno = svnb[cur^1];

        if (isv) {
            // ---- L1: v = u + (-w)@S over K=128
            float2 f0 = __half22float2(*(__half2*)&ur[0]);
            float2 f1 = __half22float2(*(__half2*)&ur[1]);
            float2 f2 = __half22float2(*(__half2*)&ur[2]);
            float2 f3 = __half22float2(*(__half2*)&ur[3]);
            float a0=f0.x,a1=f0.y,a4=f1.x,a5=f1.y,a2=f2.x,a3=f2.y,a6=f3.x,a7=f3.y;
            #pragma unroll
            for (int kc = 0; kc < 8; kc++) {
                uint32_t b00 = sSr[(g  )*68 + 8*kc     + tig];
                uint32_t b01 = sSr[(g  )*68 + 8*kc + 4 + tig];
                uint32_t b10 = sSr[(8+g)*68 + 8*kc     + tig];
                uint32_t b11 = sSr[(8+g)*68 + 8*kc + 4 + tig];
                mma16(a0,a1,a2,a3, A[kc].x,A[kc].y,A[kc].z,A[kc].w, b00,b01);
                mma16(a4,a5,a6,a7, A[kc].x,A[kc].y,A[kc].z,A[kc].w, b10,b11);
            }
            if (n + 1 < NCH) {   // prefetch next -w frags
                const uint4* Ab = (const uint4*)(g_wfh + (size_t)(cid+1)*4096) + (mr*8)*32 + l;
                #pragma unroll
                for (int j = 0; j < 8; j++) A[j] = Ab[j*32];
            }
            // publish v_new
            {
                __half* svnh = (__half*)svnw;
                int p0 = (16*mr + g) >> 1, hb = g & 1;
                svnh[((2*tig  )*36 + p0  )*2 + hb] = __float2half_rn(a0);
                svnh[((2*tig+1)*36 + p0  )*2 + hb] = __float2half_rn(a1);
                svnh[((2*tig  )*36 + p0+4)*2 + hb] = __float2half_rn(a2);
                svnh[((2*tig+1)*36 + p0+4)*2 + hb] = __float2half_rn(a3);
                svnh[((8+2*tig  )*36 + p0  )*2 + hb] = __float2half_rn(a4);
                svnh[((8+2*tig+1)*36 + p0  )*2 + hb] = __float2half_rn(a5);
                svnh[((8+2*tig  )*36 + p0+4)*2 + hb] = __float2half_rn(a6);
                svnh[((8+2*tig+1)*36 + p0+4)*2 + hb] = __float2half_rn(a7);
            }
            asm volatile("bar.sync 1, 128;" ::: "memory");   // v-warps only

            // ---- L3: S = egl*S + krT @ v_new
            {
                const float egl = segl[n];
                #pragma unroll
                for (int i = 0; i < 16; i++) S[i] *= egl;
                #pragma unroll
                for (int kc = 0; kc < 4; kc++) {
                    uint32_t b00 = svnw[(g  )*36 + 8*kc     + tig];
                    uint32_t b01 = svnw[(g  )*36 + 8*kc + 4 + tig];
                    uint32_t b10 = svnw[(8+g)*36 + 8*kc     + tig];
                    uint32_t b11 = svnw[(8+g)*36 + 8*kc + 4 + tig];
                    mma16(S[0], S[1], S[2], S[3],  K[kc  ].x,K[kc  ].y,K[kc  ].z,K[kc  ].w, b00,b01);
                    mma16(S[4], S[5], S[6], S[7],  K[kc  ].x,K[kc  ].y,K[kc  ].z,K[kc  ].w, b10,b11);
                    mma16(S[8], S[9], S[10],S[11], K[4+kc].x,K[4+kc].y,K[4+kc].z,K[4+kc].w, b00,b01);
                    mma16(S[12],S[13],S[14],S[15], K[4+kc].x,K[4+kc].y,K[4+kc].z,K[4+kc].w, b10,b11);
                }
                __half* sSh = (__half*)sSw;
                #pragma unroll
                for (int mt = 0; mt < 2; mt++) {
                    int r = 32*mr + 16*mt + g;
                    int p = r >> 1, hb2 = r & 1;
                    #pragma unroll
                    for (int nh = 0; nh < 2; nh++) {
                        int c0 = nh*8 + 2*tig;
                        const float* sp = S + mt*8 + nh*4;
                        sSh[((c0  )*68 + p  )*2 + hb2] = __float2half_rn(sp[0]);
                        sSh[((c0+1)*68 + p  )*2 + hb2] = __float2half_rn(sp[1]);
                        sSh[((c0  )*68 + p+4)*2 + hb2] = __float2half_rn(sp[2]);
                        sSh[((c0+1)*68 + p+4)*2 + hb2] = __float2half_rn(sp[3]);
                    }
                }
            }
            if (n + 1 < NCH) {   // prefetch next K, u
                const uint4* Kb = (const uint4*)(g_krfh + (size_t)(cid+1)*4096) + l;
                #pragma unroll
                for (int mt = 0; mt < 2; mt++)
                    #pragma unroll
                    for (int kc = 0; kc < 4; kc++)
                        K[mt*4+kc] = Kb[((2*mr+mt)*4 + kc)*32];
                const uint32_t* up = (const uint32_t*)(g_uh + (rb + BT + 16*mr + g)*DVD + vb);
                ur[0] = up[tig]; ur[1] = up[4+tig];
                ur[2] = up[512+tig]; ur[3] = up[512+4+tig];
            }
        } else {
            // ---- finish o(n-1): C += Aqk(n-1) @ v_new(n-1); store
            if (n > 0) {
                #pragma unroll
                for (int kc = 0; kc < 4; kc++) {
                    uint32_t b00 = svno[(g  )*36 + 8*kc     + tig];
                    uint32_t b01 = svno[(g  )*36 + 8*kc + 4 + tig];
                    uint32_t b10 = svno[(8+g)*36 + 8*kc     + tig];
                    uint32_t b11 = svno[(8+g)*36 + 8*kc + 4 + tig];
                    mma16(C[0],C[1],C[2],C[3], AF[kc].x,AF[kc].y,AF[kc].z,AF[kc].w, b00,b01);
                    mma16(C[4],C[5],C[6],C[7], AF[kc].x,AF[kc].y,AF[kc].z,AF[kc].w, b10,b11);
                }
                float* d0 = out + (rb - BT + 16*mr + g)*DVD + vb;
                float* d1 = d0 + 8*DVD;
                *(float2*)(d0 +     2*tig) = make_float2(C[0], C[1]);
                *(float2*)(d1 +     2*tig) = make_float2(C[2], C[3]);
                *(float2*)(d0 + 8 + 2*tig) = make_float2(C[4], C[5]);
                *(float2*)(d1 + 8 + 2*tig) = make_float2(C[6], C[7]);
            }
            // load this step's Aqk frags (used next step)
            {
                const uint4* Fb = (const uint4*)(g_Afh + (size_t)cid*2048) + (mr*4)*32 + l;
                #pragma unroll
                for (int kc = 0; kc < 4; kc++) AF[kc] = Fb[kc*32];
            }
            // ---- qe(n) @ S(n) into fresh C
            #pragma unroll
            for (int i = 0; i < 8; i++) C[i] = 0.f;
            #pragma unroll
            for (int kc = 0; kc < 8; kc++) {
                uint32_t b00 = sSr[(g  )*68 + 8*kc     + tig];
                uint32_t b01 = sSr[(g  )*68 + 8*kc + 4 + tig];
                uint32_t b10 = sSr[(8+g)*68 + 8*kc     + tig];
                uint32_t b11 = sSr[(8+g)*68 + 8*kc + 4 + tig];
                mma16(C[0],C[1],C[2],C[3], A[kc].x,A[kc].y,A[kc].z,A[kc].w, b00,b01);
                mma16(C[4],C[5],C[6],C[7], A[kc].x,A[kc].y,A[kc].z,A[kc].w, b10,b11);
            }
            if (n + 1 < NCH) {   // prefetch next qe frags
                const uint4* Ab = (const uint4*)(g_qefh + (size_t)(cid+1)*4096) + (mr*8)*32 + l;
                #pragma unroll
                for (int j = 0; j < 8; j++) A[j] = Ab[j*32];
            }
        }
        __syncthreads();   // publishes sS[cur^1] + svn[cur]; retires svn[cur^1]
    }

    // o epilogue: finish the last chunk
    if (!isv) {
        uint32_t* svno = svnb[(NCH-1) & 1];
        #pragma unroll
        for (int kc = 0; kc < 4; kc++) {
            uint32_t b00 = svno[(g  )*36 + 8*kc     + tig];
            uint32_t b01 = svno[(g  )*36 + 8*kc + 4 + tig];
            uint32_t b10 = svno[(8+g)*36 + 8*kc     + tig];
            uint32_t b11 = svno[(8+g)*36 + 8*kc + 4 + tig];
            mma16(C[0],C[1],C[2],C[3], AF[kc].x,AF[kc].y,AF[kc].z,AF[kc].w, b00,b01);
            mma16(C[4],C[5],C[6],C[7], AF[kc].x,AF[kc].y,AF[kc].z,AF[kc].w, b10,b11);
        }
        float* d0 = out + ((size_t)bh*SEQ + (size_t)(NCH-1)*BT + 16*mr + g)*DVD + vb;
        float* d1 = d0 + 8*DVD;
        *(float2*)(d0 +     2*tig) = make_float2(C[0], C[1]);
        *(float2*)(d1 +     2*tig) = make_float2(C[2], C[3]);
        *(float2*)(d0 + 8 + 2*tig) = make_float2(C[4], C[5]);
        *(float2*)(d1 + 8 + 2*tig) = make_float2(C[6], C[7]);
    }

    if (write_sf && isv) {
        float* base = out + OSZ + (size_t)bh*DKD*DVD + vb;
        #pragma unroll
        for (int mt = 0; mt < 2; mt++) {
            int r = 32*mr + 16*mt + g;
            #pragma unroll
            for (int nh = 0; nh < 2; nh++) {
                const float* sp = S + mt*8 + nh*4;
                *(float2*)(base + (size_t)(r    )*DVD + nh*8 + 2*tig) = make_float2(sp[0], sp[1]);
                *(float2*)(base + (size_t)(r + 8)*DVD + nh*8 + 2*tig) = make_float2(sp[2], sp[3]);
            }
        }
    }
}

// ---------------------------------------------------------------------------
extern "C" void kernel_launch(void* const* d_in, const int* in_sizes, int n_in,
                              void* d_out, int out_size)
{
    const float* q    = (const float*)d_in[0];
    const float* k    = (const float*)d_in[1];
    const float* v    = (const float*)d_in[2];
    const float* g    = (const float*)d_in[3];
    const float* beta = (const float*)d_in[4];
    float* out = (float*)d_out;

    cudaFuncSetAttribute(p1_kernel, cudaFuncAttributeMaxDynamicSharedMemorySize, P1_SMEM);

    p1_kernel<<<NCHUNKS, 256, P1_SMEM>>>(q, k, v, g, beta);

    int wsf = (out_size > OSZ) ? 1 : 0;
    p2_kernel<<<BHT*8, 256>>>(out, wsf);
}

// round 10
// speedup vs baseline: 3.8798x; 1.0696x over previous
#include <cuda_runtime.h>
#include <cuda_fp16.h>
#include <cstdint>

// Problem constants (fixed by setup_inputs)
#define SEQ  8192
#define DKD  128
#define DVD  128
#define BT   64
#define NCH  128          // SEQ/BT
#define BHT  16           // BB*HHD
#define NCHUNKS 2048      // BHT*NCH
#define OSZ  16777216     // BHT*SEQ*DVD  (size of o)

// ---- fp16 helpers ----
__device__ __forceinline__ uint32_t h2(float lo, float hi) {
    __half2 h = __floats2half2_rn(lo, hi);
    return *reinterpret_cast<uint32_t*>(&h);
}
__device__ __forceinline__ void mma16(float& d0, float& d1, float& d2, float& d3,
    uint32_t a0, uint32_t a1, uint32_t a2, uint32_t a3, uint32_t b0, uint32_t b1) {
    asm("mma.sync.aligned.m16n8k16.row.col.f32.f16.f16.f32 "
        "{%0,%1,%2,%3},{%4,%5,%6,%7},{%8,%9},{%0,%1,%2,%3};"
        : "+f"(d0), "+f"(d1), "+f"(d2), "+f"(d3)
        : "r"(a0), "r"(a1), "r"(a2), "r"(a3), "r"(b0), "r"(b1));
}

// Scratch (device globals; fp16 fragment-major, half2 packed along K)
__device__ uint32_t g_wfh [NCHUNKS*4096];  // -w   64x128: block b = mr*8 + kc(8)
__device__ uint32_t g_qefh[NCHUNKS*4096];  // qe   64x128: same blocks
__device__ uint32_t g_krfh[NCHUNKS*4096];  // krT 128x64 : block b = cr*4 + kc(4)
__device__ uint32_t g_Afh [NCHUNKS*2048];  // Aqk  64x64 : block b = mr*4 + kc(4)
__device__ __half   g_uh  [BHT*SEQ*DVD];   // u fp16 [row][V]
__device__ float    g_egl [NCHUNKS];

#define P1_SMEM ((8704*2 + 4352 + 3*64)*4)

// ---------------------------------------------------------------------------
// Phase 1: per-chunk (2048 CTAs). Both 64x64 gram matmuls (A0, Aqk) on fp16
// mma; A0 scaled+stored fp32 to smem for the (fp32) triangular solve.
// ---------------------------------------------------------------------------
__global__ void __launch_bounds__(256, 2) p1_kernel(
    const float* __restrict__ q, const float* __restrict__ k,
    const float* __restrict__ v, const float* __restrict__ g,
    const float* __restrict__ beta)
{
    extern __shared__ float sm[];
    float* skT = sm;                 // [128][68] k transposed (normalized)
    float* sqT = skT + 8704;         // [128][68] q transposed; later: -w staged
    float* sA0 = sqT + 8704;         // [64][68]  strictly-lower A0 (fp32)
    float* seg = sA0 + 4352;         // [64] exp(cumsum g)
    float* sie = seg + 64;           // [64] 1/seg
    float* sb  = sie + 64;           // [64] beta
    __shared__ float sgr[BT];

    const int cid = blockIdx.x;
    const int bh  = cid / NCH, n = cid % NCH;
    const int rowbase = bh*SEQ + n*BT;
    const int t = threadIdx.x;
    const int lane = t & 31, wid = t >> 5;
    const int gq = lane >> 2, tig = lane & 3;

    if (t < BT) { sb[t] = beta[rowbase + t]; sgr[t] = g[rowbase + t]; }
    __syncthreads();
    if (t < 32) {
        float a = sgr[2*t], b = sgr[2*t+1];
        float s = a + b;
        #pragma unroll
        for (int o = 1; o < 32; o <<= 1) {
            float y = __shfl_up_sync(0xffffffffu, s, o);
            if (t >= o) s += y;
        }
        float gc1 = s, gc0 = s - b;
        seg[2*t  ] = __expf(gc0);  sie[2*t  ] = __expf(-gc0);
        seg[2*t+1] = __expf(gc1);  sie[2*t+1] = __expf(-gc1);
        if (t == 31) g_egl[cid] = seg[63];
    }
    // normalize rows of q,k; store transposed
    for (int r = wid; r < BT; r += 8) {
        const float* kp = k + (size_t)(rowbase + r)*DKD;
        const float* qp = q + (size_t)(rowbase + r)*DKD;
        float k0=kp[lane],k1=kp[lane+32],k2=kp[lane+64],k3=kp[lane+96];
        float q0=qp[lane],q1=qp[lane+32],q2=qp[lane+64],q3=qp[lane+96];
        float ssk = k0*k0+k1*k1+k2*k2+k3*k3;
        float ssq = q0*q0+q1*q1+q2*q2+q3*q3;
        #pragma unroll
        for (int o = 16; o; o >>= 1) {
            ssk += __shfl_xor_sync(0xffffffffu, ssk, o);
            ssq += __shfl_xor_sync(0xffffffffu, ssq, o);
        }
        float ik = 1.f/(sqrtf(ssk)+1e-6f);
        float iq = 0.08838834764831845f/(sqrtf(ssq)+1e-6f);  // K^-0.5 folded in
        skT[(lane    )*68+r]=k0*ik; skT[(lane+32)*68+r]=k1*ik;
        skT[(lane+64)*68+r]=k2*ik; skT[(lane+96)*68+r]=k3*ik;
        sqT[(lane    )*68+r]=q0*iq; sqT[(lane+32)*68+r]=q1*iq;
        sqT[(lane+64)*68+r]=q2*iq; sqT[(lane+96)*68+r]=q3*iq;
    }
    __syncthreads();

    // ---- warps 0-3: Aqk = q·k^T via mma -> g_Afh; then qef emit
    //      warps 4-7: A0  = k·k^T via mma -> sA0 (fp32, lower tri); then krf
    if (wid < 4) {
        const int mr = wid;
        const int i0 = 16*mr + gq, i8 = i0 + 8;
        float D[8][4];
        #pragma unroll
        for (int z = 0; z < 8; z++) { D[z][0]=0.f; D[z][1]=0.f; D[z][2]=0.f; D[z][3]=0.f; }
        #pragma unroll
        for (int kc = 0; kc < 8; kc++) {
            int kb = 16*kc;
            uint32_t a0 = h2(sqT[(kb+2*tig  )*68+i0], sqT[(kb+2*tig+1)*68+i0]);
            uint32_t a1 = h2(sqT[(kb+2*tig  )*68+i8], sqT[(kb+2*tig+1)*68+i8]);
            uint32_t a2 = h2(sqT[(kb+2*tig+8)*68+i0], sqT[(kb+2*tig+9)*68+i0]);
            uint32_t a3 = h2(sqT[(kb+2*tig+8)*68+i8], sqT[(kb+2*tig+9)*68+i8]);
            #pragma unroll
            for (int nt = 0; nt < 8; nt++) {
                int jn = 8*nt + gq;
                uint32_t b0 = h2(skT[(kb+2*tig  )*68+jn], skT[(kb+2*tig+1)*68+jn]);
                uint32_t b1 = h2(skT[(kb+2*tig+8)*68+jn], skT[(kb+2*tig+9)*68+jn]);
                mma16(D[nt][0],D[nt][1],D[nt][2],D[nt][3], a0,a1,a2,a3, b0,b1);
            }
        }
        float s_i0 = seg[i0], s_i8 = seg[i8];
        #pragma unroll
        for (int c = 0; c < 4; c++) {
            int j0 = 16*c + 2*tig;
            float f00 = (j0   < i0) ? s_i0*sie[j0  ] : ((j0  ==i0)?1.f:0.f);
            float f01 = (j0+1 < i0) ? s_i0*sie[j0+1] : ((j0+1==i0)?1.f:0.f);
            float f80 = (j0   < i8) ? s_i8*sie[j0  ] : ((j0  ==i8)?1.f:0.f);
            float f81 = (j0+1 < i8) ? s_i8*sie[j0+1] : ((j0+1==i8)?1.f:0.f);
            float h00 = (j0+8 < i0) ? s_i0*sie[j0+8] : ((j0+8==i0)?1.f:0.f);
            float h01 = (j0+9 < i0) ? s_i0*sie[j0+9] : ((j0+9==i0)?1.f:0.f);
            float h80 = (j0+8 < i8) ? s_i8*sie[j0+8] : ((j0+8==i8)?1.f:0.f);
            float h81 = (j0+9 < i8) ? s_i8*sie[j0+9] : ((j0+9==i8)?1.f:0.f);
            uint4 o;
            o.x = h2(D[2*c  ][0]*f00, D[2*c  ][1]*f01);
            o.y = h2(D[2*c  ][2]*f80, D[2*c  ][3]*f81);
            o.z = h2(D[2*c+1][0]*h00, D[2*c+1][1]*h01);
            o.w = h2(D[2*c+1][2]*h80, D[2*c+1][3]*h81);
            *(uint4*)&g_Afh[(size_t)cid*2048 + (mr*4+c)*128 + lane*4] = o;
        }
        // qef emit
        for (int task = t; task < 1024; task += 128) {
            int b = task >> 5, l = task & 31;
            int ii = 16*(b>>3) + (l>>2), k0 = 16*(b&7) + (l&3)*2;
            float s0 = seg[ii], s1 = seg[ii+8];
            uint4 o;
            o.x = h2(sqT[(k0  )*68+ii  ]*s0, sqT[(k0+1)*68+ii  ]*s0);
            o.y = h2(sqT[(k0  )*68+ii+8]*s1, sqT[(k0+1)*68+ii+8]*s1);
            o.z = h2(sqT[(k0+8)*68+ii  ]*s0, sqT[(k0+9)*68+ii  ]*s0);
            o.w = h2(sqT[(k0+8)*68+ii+8]*s1, sqT[(k0+9)*68+ii+8]*s1);
            *(uint4*)&g_qefh[(size_t)cid*4096 + b*128 + l*4] = o;
        }
    } else {
        const int mr = wid - 4;
        const int i0 = 16*mr + gq, i8 = i0 + 8;
        float D[8][4];
        #pragma unroll
        for (int z = 0; z < 8; z++) { D[z][0]=0.f; D[z][1]=0.f; D[z][2]=0.f; D[z][3]=0.f; }
        #pragma unroll
        for (int kc = 0; kc < 8; kc++) {
            int kb = 16*kc;
            uint32_t a0 = h2(skT[(kb+2*tig  )*68+i0], skT[(kb+2*tig+1)*68+i0]);
            uint32_t a1 = h2(skT[(kb+2*tig  )*68+i8], skT[(kb+2*tig+1)*68+i8]);
            uint32_t a2 = h2(skT[(kb+2*tig+8)*68+i0], skT[(kb+2*tig+9)*68+i0]);
            uint32_t a3 = h2(skT[(kb+2*tig+8)*68+i8], skT[(kb+2*tig+9)*68+i8]);
            #pragma unroll
            for (int nt = 0; nt < 8; nt++) {
                int jn = 8*nt + gq;
                uint32_t b0 = h2(skT[(kb+2*tig  )*68+jn], skT[(kb+2*tig+1)*68+jn]);
                uint32_t b1 = h2(skT[(kb+2*tig+8)*68+jn], skT[(kb+2*tig+9)*68+jn]);
                mma16(D[nt][0],D[nt][1],D[nt][2],D[nt][3], a0,a1,a2,a3, b0,b1);
            }
        }
        // scale + store strict lower triangle (fp32)
        float bs0 = seg[i0]*sb[i0], bs8 = seg[i8]*sb[i8];
        #pragma unroll
        for (int nt = 0; nt < 8; nt++) {
            int j0 = 8*nt + 2*tig;
            if (j0   < i0) sA0[i0*68+j0  ] = D[nt][0]*bs0*sie[j0  ];
            if (j0+1 < i0) sA0[i0*68+j0+1] = D[nt][1]*bs0*sie[j0+1];
            if (j0   < i8) sA0[i8*68+j0  ] = D[nt][2]*bs8*sie[j0  ];
            if (j0+1 < i8) sA0[i8*68+j0+1] = D[nt][3]*bs8*sie[j0+1];
        }
        // krf emit
        float egl2 = seg[BT-1];
        for (int task = t - 128; task < 1024; task += 128) {
            int b = task >> 5, l = task & 31;
            int c0 = 16*(b>>2) + (l>>2), ii = 16*(b&3) + (l&3)*2;
            float e0 = egl2*sie[ii], e1 = egl2*sie[ii+1];
            float e8 = egl2*sie[ii+8], e9 = egl2*sie[ii+9];
            uint4 o;
            o.x = h2(skT[(c0  )*68+ii  ]*e0, skT[(c0  )*68+ii+1]*e1);
            o.y = h2(skT[(c0+8)*68+ii  ]*e0, skT[(c0+8)*68+ii+1]*e1);
            o.z = h2(skT[(c0  )*68+ii+8]*e8, skT[(c0  )*68+ii+9]*e9);
            o.w = h2(skT[(c0+8)*68+ii+8]*e8, skT[(c0+8)*68+ii+9]*e9);
            *(uint4*)&g_krfh[(size_t)cid*4096 + b*128 + l*4] = o;
        }
    }
    __syncthreads();   // sA0 ready; emits done before sqT is overwritten

    // Unit-lower triangular solve (fp32)
    {
        float x[64];
        if (t < 128) {
            #pragma unroll
            for (int i = 0; i < 64; i++) x[i] = sb[i]*skT[t*68+i]*seg[i];
        } else {
            const float* vp = v + (size_t)rowbase*DVD + (t - 128);
            #pragma unroll
            for (int i = 0; i < 64; i++) x[i] = sb[i]*vp[i*DVD];
        }
        #pragma unroll
        for (int i = 1; i < 64; i++) {
            float s0 = 0.f, s1 = 0.f, s2 = 0.f, s3 = 0.f;
            int j = 0;
            #pragma unroll
            for (; j + 4 <= i; j += 4) {
                float4 a4 = *(const float4*)&sA0[i*68+j];
                s0 += a4.x*x[j]; s1 += a4.y*x[j+1];
                s2 += a4.z*x[j+2]; s3 += a4.w*x[j+3];
            }
            #pragma unroll
            for (; j < i; j++) s0 += sA0[i*68+j]*x[j];
            x[i] -= (s0 + s1) + (s2 + s3);
        }
        if (t < 128) {
            #pragma unroll
            for (int i = 0; i < 64; i++) sqT[t*68+i] = -x[i];   // stage NEGATED w
        } else {
            #pragma unroll
            for (int i = 0; i < 64; i++)
                g_uh[(size_t)(rowbase+i)*DVD + (t-128)] = __float2half_rn(x[i]);
        }
    }
    __syncthreads();

    // -w fragment emit (all 256 threads)
    for (int task = t; task < 1024; task += 256) {
        int b = task >> 5, l = task & 31;
        int i0 = 16*(b>>3) + (l>>2), k0 = 16*(b&7) + (l&3)*2;
        uint4 o;
        o.x = h2(sqT[(k0  )*68+i0  ], sqT[(k0+1)*68+i0  ]);
        o.y = h2(sqT[(k0  )*68+i0+8], sqT[(k0+1)*68+i0+8]);
        o.z = h2(sqT[(k0+8)*68+i0  ], sqT[(k0+9)*68+i0  ]);
        o.w = h2(sqT[(k0+8)*68+i0+8], sqT[(k0+9)*68+i0+8]);
        *(uint4*)&g_wfh[(size_t)cid*4096 + b*128 + l*4] = o;
    }
}

// ---------------------------------------------------------------------------
// Phase 2: fp16 mma recurrence, software-pipelined (PROVEN R8 structure).
// Double-buffered sS/svn; ONE full barrier per step + a v-warps-only named
// barrier. o-warps run one step behind (carry qe@S partial + Aqk frags).
// ---------------------------------------------------------------------------
__global__ void __launch_bounds__(256, 1) p2_kernel(float* __restrict__ out, int write_sf)
{
    __shared__ uint32_t sSb [2][16*68];   // S mirror, double buffered
    __shared__ uint32_t svnb[2][16*36];   // v_new, double buffered
    __shared__ float    segl[NCH];

    const int t = threadIdx.x;
    const int w = t >> 5, l = t & 31, g = l >> 2, tig = l & 3;
    const bool isv = (w < 4);
    const int mr = w & 3;
    const int bh = blockIdx.x >> 3;
    const int vb = (blockIdx.x & 7) * 16;

    for (int i = t; i < 16*68; i += 256) sSb[0][i] = 0u;
    if (t < NCH) segl[t] = g_egl[bh*NCH + t];
    __syncthreads();

    float S[16];                       // v-warps: persistent fp32 state strip
    #pragma unroll
    for (int i = 0; i < 16; i++) S[i] = 0.f;
    float C[8];                        // o-warps: carried o accumulator
    uint4 AF[4];                       // o-warps: carried Aqk frags (prev step)
    uint4 A[8];                        // L1 A frags (prefetched)
    uint4 K[8];                        // v-warps: krT frags (prefetched)
    uint32_t ur[4];                    // v-warps: u half2 regs (prefetched)

    const uint32_t* aL1 = isv ? g_wfh : g_qefh;
    {
        const uint4* Ab = (const uint4*)(aL1 + (size_t)(bh*NCH)*4096) + (mr*8)*32 + l;
        #pragma unroll
        for (int j = 0; j < 8; j++) A[j] = Ab[j*32];
        if (isv) {
            const uint4* Kb = (const uint4*)(g_krfh + (size_t)(bh*NCH)*4096) + l;
            #pragma unroll
            for (int mt = 0; mt < 2; mt++)
                #pragma unroll
                for (int kc = 0; kc < 4; kc++)
                    K[mt*4+kc] = Kb[((2*mr+mt)*4 + kc)*32];
            const uint32_t* up = (const uint32_t*)(g_uh + (size_t)(bh*SEQ + 16*mr + g)*DVD + vb);
            ur[0] = up[tig]; ur[1] = up[4+tig];
            ur[2] = up[512+tig]; ur[3] = up[512+4+tig];
        }
    }

    for (int n = 0; n < NCH; n++) {
        const int cid = bh*NCH + n;
        const size_t rb = (size_t)bh*SEQ + (size_t)n*BT;
        const int cur = n & 1;
        uint32_t* sSr  = sSb[cur];
        uint32_t* sSw  = sSb[cur^1];
        uint32_t* svnw = svnb[cur];
        uint32_t* svno = svnb[cur^1];

        if (isv) {
            // ---- L1: v = u + (-w)@S over K=128
            float2 f0 = __half22float2(*(__half2*)&ur[0]);
            float2 f1 = __half22float2(*(__half2*)&ur[1]);
            float2 f2 = __half22float2(*(__half2*)&ur[2]);
            float2 f3 = __half22float2(*(__half2*)&ur[3]);
            float a0=f0.x,a1=f0.y,a4=f1.x,a5=f1.y,a2=f2.x,a3=f2.y,a6=f3.x,a7=f3.y;
            #pragma unroll
            for (int kc = 0; kc < 8; kc++) {
                uint32_t b00 = sSr[(g  )*68 + 8*kc     + tig];
                uint32_t b01 = sSr[(g  )*68 + 8*kc + 4 + tig];
                uint32_t b10 = sSr[(8+g)*68 + 8*kc     + tig];
                uint32_t b11 = sSr[(8+g)*68 + 8*kc + 4 + tig];
                mma16(a0,a1,a2,a3, A[kc].x,A[kc].y,A[kc].z,A[kc].w, b00,b01);
                mma16(a4,a5,a6,a7, A[kc].x,A[kc].y,A[kc].z,A[kc].w, b10,b11);
            }
            if (n + 1 < NCH) {   // prefetch next -w frags
                const uint4* Ab = (const uint4*)(g_wfh + (size_t)(cid+1)*4096) + (mr*8)*32 + l;
                #pragma unroll
                for (int j = 0; j < 8; j++) A[j] = Ab[j*32];
            }
            // publish v_new
            {
                __half* svnh = (__half*)svnw;
                int p0 = (16*mr + g) >> 1, hb = g & 1;
                svnh[((2*tig  )*36 + p0  )*2 + hb] = __float2half_rn(a0);
                svnh[((2*tig+1)*36 + p0  )*2 + hb] = __float2half_rn(a1);
                svnh[((2*tig  )*36 + p0+4)*2 + hb] = __float2half_rn(a2);
                svnh[((2*tig+1)*36 + p0+4)*2 + hb] = __float2half_rn(a3);
                svnh[((8+2*tig  )*36 + p0  )*2 + hb] = __float2half_rn(a4);
                svnh[((8+2*tig+1)*36 + p0  )*2 + hb] = __float2half_rn(a5);
                svnh[((8+2*tig  )*36 + p0+4)*2 + hb] = __float2half_rn(a6);
                svnh[((8+2*tig+1)*36 + p0+4)*2 + hb] = __float2half_rn(a7);
            }
            asm volatile("bar.sync 1, 128;" ::: "memory");   // v-warps only

            // ---- L3: S = egl*S + krT @ v_new
            {
                const float egl = segl[n];
                #pragma unroll
                for (int i = 0; i < 16; i++) S[i] *= egl;
                #pragma unroll
                for (int kc = 0; kc < 4; kc++) {
                    uint32_t b00 = svnw[(g  )*36 + 8*kc     + tig];
                    uint32_t b01 = svnw[(g  )*36 + 8*kc + 4 + tig];
                    uint32_t b10 = svnw[(8+g)*36 + 8*kc     + tig];
                    uint32_t b11 = svnw[(8+g)*36 + 8*kc + 4 + tig];
                    mma16(S[0], S[1], S[2], S[3],  K[kc  ].x,K[kc  ].y,K[kc  ].z,K[kc  ].w, b00,b01);
                    mma16(S[4], S[5], S[6], S[7],  K[kc  ].x,K[kc  ].y,K[kc  ].z,K[kc  ].w, b10,b11);
                    mma16(S[8], S[9], S[10],S[11], K[4+kc].x,K[4+kc].y,K[4+kc].z,K[4+kc].w, b00,b01);
                    mma16(S[12],S[13],S[14],S[15], K[4+kc].x,K[4+kc].y,K[4+kc].z,K[4+kc].w, b10,b11);
                }
                __half* sSh = (__half*)sSw;
                #pragma unroll
                for (int mt = 0; mt < 2; mt++) {
                    int r = 32*mr + 16*mt + g;
                    int p = r >> 1, hb2 = r & 1;
                    #pragma unroll
                    for (int nh = 0; nh < 2; nh++) {
                        int c0 = nh*8 + 2*tig;
                        const float* sp = S + mt*8 + nh*4;
                        sSh[((c0  )*68 + p  )*2 + hb2] = __float2half_rn(sp[0]);
                        sSh[((c0+1)*68 + p  )*2 + hb2] = __float2half_rn(sp[1]);
                        sSh[((c0  )*68 + p+4)*2 + hb2] = __float2half_rn(sp[2]);
                        sSh[((c0+1)*68 + p+4)*2 + hb2] = __float2half_rn(sp[3]);
                    }
                }
            }
            if (n + 1 < NCH) {   // prefetch next K, u
                const uint4* Kb = (const uint4*)(g_krfh + (size_t)(cid+1)*4096) + l;
                #pragma unroll
                for (int mt = 0; mt < 2; mt++)
                    #pragma unroll
                    for (int kc = 0; kc < 4; kc++)
                        K[mt*4+kc] = Kb[((2*mr+mt)*4 + kc)*32];
                const uint32_t* up = (const uint32_t*)(g_uh + (rb + BT + 16*mr + g)*DVD + vb);
                ur[0] = up[tig]; ur[1] = up[4+tig];
                ur[2] = up[512+tig]; ur[3] = up[512+4+tig];
            }
        } else {
            // ---- finish o(n-1): C += Aqk(n-1) @ v_new(n-1); store
            if (n > 0) {
                #pragma unroll
                for (int kc = 0; kc < 4; kc++) {
                    uint32_t b00 = svno[(g  )*36 + 8*kc     + tig];
                    uint32_t b01 = svno[(g  )*36 + 8*kc + 4 + tig];
                    uint32_t b10 = svno[(8+g)*36 + 8*kc     + tig];
                    uint32_t b11 = svno[(8+g)*36 + 8*kc + 4 + tig];
                    mma16(C[0],C[1],C[2],C[3], AF[kc].x,AF[kc].y,AF[kc].z,AF[kc].w, b00,b01);
                    mma16(C[4],C[5],C[6],C[7], AF[kc].x,AF[kc].y,AF[kc].z,AF[kc].w, b10,b11);
                }
                float* d0 = out + (rb - BT + 16*mr + g)*DVD + vb;
                float* d1 = d0 + 8*DVD;
                *(float2*)(d0 +     2*tig) = make_float2(C[0], C[1]);
                *(float2*)(d1 +     2*tig) = make_float2(C[2], C[3]);
                *(float2*)(d0 + 8 + 2*tig) = make_float2(C[4], C[5]);
                *(float2*)(d1 + 8 + 2*tig) = make_float2(C[6], C[7]);
            }
            // load this step's Aqk frags (used next step)
            {
                const uint4* Fb = (const uint4*)(g_Afh + (size_t)cid*2048) + (mr*4)*32 + l;
                #pragma unroll
                for (int kc = 0; kc < 4; kc++) AF[kc] = Fb[kc*32];
            }
            // ---- qe(n) @ S(n) into fresh C
            #pragma unroll
            for (int i = 0; i < 8; i++) C[i] = 0.f;
            #pragma unroll
            for (int kc = 0; kc < 8; kc++) {
                uint32_t b00 = sSr[(g  )*68 + 8*kc     + tig];
                uint32_t b01 = sSr[(g  )*68 + 8*kc + 4 + tig];
                uint32_t b10 = sSr[(8+g)*68 + 8*kc     + tig];
                uint32_t b11 = sSr[(8+g)*68 + 8*kc + 4 + tig];
                mma16(C[0],C[1],C[2],C[3], A[kc].x,A[kc].y,A[kc].z,A[kc].w, b00,b01);
                mma16(C[4],C[5],C[6],C[7], A[kc].x,A[kc].y,A[kc].z,A[kc].w, b10,b11);
            }
            if (n + 1 < NCH) {   // prefetch next qe frags
                const uint4* Ab = (const uint4*)(g_qefh + (size_t)(cid+1)*4096) + (mr*8)*32 + l;
                #pragma unroll
                for (int j = 0; j < 8; j++) A[j] = Ab[j*32];
            }
        }
        __syncthreads();   // publishes sS[cur^1] + svn[cur]; retires svn[cur^1]
    }

    // o epilogue: finish the last chunk
    if (!isv) {
        uint32_t* svno = svnb[(NCH-1) & 1];
        #pragma unroll
        for (int kc = 0; kc < 4; kc++) {
            uint32_t b00 = svno[(g  )*36 + 8*kc     + tig];
            uint32_t b01 = svno[(g  )*36 + 8*kc + 4 + tig];
            uint32_t b10 = svno[(8+g)*36 + 8*kc     + tig];
            uint32_t b11 = svno[(8+g)*36 + 8*kc + 4 + tig];
            mma16(C[0],C[1],C[2],C[3], AF[kc].x,AF[kc].y,AF[kc].z,AF[kc].w, b00,b01);
            mma16(C[4],C[5],C[6],C[7], AF[kc].x,AF[kc].y,AF[kc].z,AF[kc].w, b10,b11);
        }
        float* d0 = out + ((size_t)bh*SEQ + (size_t)(NCH-1)*BT + 16*mr + g)*DVD + vb;
        float* d1 = d0 + 8*DVD;
        *(float2*)(d0 +     2*tig) = make_float2(C[0], C[1]);
        *(float2*)(d1 +     2*tig) = make_float2(C[2], C[3]);
        *(float2*)(d0 + 8 + 2*tig) = make_float2(C[4], C[5]);
        *(float2*)(d1 + 8 + 2*tig) = make_float2(C[6], C[7]);
    }

    if (write_sf && isv) {
        float* base = out + OSZ + (size_t)bh*DKD*DVD + vb;
        #pragma unroll
        for (int mt = 0; mt < 2; mt++) {
            int r = 32*mr + 16*mt + g;
            #pragma unroll
            for (int nh = 0; nh < 2; nh++) {
                const float* sp = S + mt*8 + nh*4;
                *(float2*)(base + (size_t)(r    )*DVD + nh*8 + 2*tig) = make_float2(sp[0], sp[1]);
                *(float2*)(base + (size_t)(r + 8)*DVD + nh*8 + 2*tig) = make_float2(sp[2], sp[3]);
            }
        }
    }
}

// ---------------------------------------------------------------------------
extern "C" void kernel_launch(void* const* d_in, const int* in_sizes, int n_in,
                              void* d_out, int out_size)
{
    const float* q    = (const float*)d_in[0];
    const float* k    = (const float*)d_in[1];
    const float* v    = (const float*)d_in[2];
    const float* g    = (const float*)d_in[3];
    const float* beta = (const float*)d_in[4];
    float* out = (float*)d_out;

    cudaFuncSetAttribute(p1_kernel, cudaFuncAttributeMaxDynamicSharedMemorySize, P1_SMEM);

    p1_kernel<<<NCHUNKS, 256, P1_SMEM>>>(q, k, v, g, beta);

    int wsf = (out_size > OSZ) ? 1 : 0;
    p2_kernel<<<BHT*8, 256>>>(out, wsf);
}